// round 8
// baseline (speedup 1.0000x reference)
// BitNet-style FFN on GB300 — sm_103 baseline-ISA build (tcgen05 rejected by the
// harness's ptxas target). cp.async + ldmatrix + mma.sync.m16n8k16.f32.f16.f16.f32.
//   out = gelu_exact(x @ T(W1)^T + b1) @ T(W2)^T + b2,  T() = absmean ternary {-1,0,1}
// Ternary weights EXACT in fp16; x/H fp16, fp32 accumulators -> rel_err ~3e-4.
// R8: 512 threads / 16 warps (4 per SMSP), warp tile 64x32, CTA tile 256x128.
//     Same RF footprint (64 acc/thread) but 2x the warps -> hides the LDSM->MMA
//     latency that left the tensor pipe 46% idle at R7's 8-warp occupancy.

#include <cuda_runtime.h>
#include <cuda_fp16.h>
#include <cstdint>

#define EMB 1024
#define FF 4096
#define NTOK 8192
#define WN (FF * EMB)
#define XN (NTOK * EMB)

// ---------------- device-global scratch (allocation-free rule) ----------------
__device__ __align__(16) __half g_Xh[(size_t)NTOK * EMB];   // 16 MB
__device__ __align__(16) __half g_W1t[(size_t)FF * EMB];    // 8 MB
__device__ __align__(16) __half g_W2t[(size_t)FF * EMB];    // 8 MB
__device__ __align__(16) __half g_H[(size_t)NTOK * FF];     // 64 MB
__device__ float g_partial[2048];
__device__ float g_scale[2];

// ---------------- PTX helpers (baseline ISA only) ----------------
__device__ __forceinline__ uint32_t smem_u32(const void* p) {
    uint32_t a;
    asm("{ .reg .u64 t; cvta.to.shared.u64 t, %1; cvt.u32.u64 %0, t; }" : "=r"(a) : "l"(p));
    return a;
}

#define CP16(dst, src) \
    asm volatile("cp.async.cg.shared.global [%0], [%1], 16;" \
                 :: "r"((uint32_t)(dst)), "l"(__cvta_generic_to_global(src)) : "memory")
#define CP_COMMIT()  asm volatile("cp.async.commit_group;" ::: "memory")
#define CP_WAIT2()   asm volatile("cp.async.wait_group 2;" ::: "memory")

#define LDSM4(r0, r1, r2, r3, addr) \
    asm volatile("ldmatrix.sync.aligned.m8n8.x4.shared.b16 {%0,%1,%2,%3}, [%4];" \
                 : "=r"(r0), "=r"(r1), "=r"(r2), "=r"(r3) : "r"(addr))

#define MMA16816(d, a0, a1, a2, a3, b0, b1) \
    asm volatile("mma.sync.aligned.m16n8k16.row.col.f32.f16.f16.f32 " \
                 "{%0,%1,%2,%3}, {%4,%5,%6,%7}, {%8,%9}, {%0,%1,%2,%3};" \
                 : "+f"((d)[0]), "+f"((d)[1]), "+f"((d)[2]), "+f"((d)[3]) \
                 : "r"(a0), "r"(a1), "r"(a2), "r"(a3), "r"(b0), "r"(b1))

// ---------------- GEMM configuration ----------------
constexpr int BM = 256, BN = 128, BK = 64, NST = 4, TPB = 512;
constexpr int A_BYTES = BM * 128;            // 32 KB (256 rows x 64 halves = 128 B/row)
constexpr int B_BYTES = BN * 128;            // 16 KB
constexpr int STG_BYTES = A_BYTES + B_BYTES; // 48 KB
constexpr int SM_BIAS = 0, SM_TILES = 2048;
constexpr int SMEM_TOTAL = SM_TILES + NST * STG_BYTES;   // 198656 B

// Per-stage tile loader. A and B both K-major, 64 halves (= 8 x 16B segs) per row.
// SW128 swizzle: seg' = seg ^ (row & 7) -> conflict-free cp.async + ldmatrix.
__device__ __forceinline__ void load_tile(uint32_t sb, int stage,
                                          const __half* __restrict__ A,
                                          const __half* __restrict__ B,
                                          int m0, int n0, int kc, int K, int tid) {
    uint32_t sa = sb + SM_TILES + stage * STG_BYTES;
    uint32_t sB = sa + A_BYTES;
    #pragma unroll
    for (int t = 0; t < 4; t++) {            // A: 256 rows x 8 segs = 2048 chunks
        int i = tid + t * TPB;
        int r = i >> 3, s = i & 7;
        uint32_t dst = sa + r * 128 + ((s ^ (r & 7)) << 4);
        CP16(dst, A + (size_t)(m0 + r) * K + kc + s * 8);
    }
    #pragma unroll
    for (int t = 0; t < 2; t++) {            // B: 128 rows x 8 segs = 1024 chunks
        int i = tid + t * TPB;
        int r = i >> 3, s = i & 7;
        uint32_t dst = sB + r * 128 + ((s ^ (r & 7)) << 4);
        CP16(dst, B + (size_t)(n0 + r) * K + kc + s * 8);
    }
}

// ---------------- fused GEMM + epilogue ----------------
// GELU=true : A=g_Xh [8192,1024], B=g_W1t [4096,1024], out=g_H (fp16), +b1, erf-GELU
// GELU=false: A=g_H  [8192,4096], B=g_W2t [1024,4096], out=out_f (fp32), +b2
template <bool GELU>
__global__ void __launch_bounds__(TPB, 1)
ffn_gemm(const float* __restrict__ bias, float* __restrict__ out_f) {
    extern __shared__ __align__(1024) uint8_t smem_raw[];
    uint32_t sb = smem_u32(smem_raw);
    const int tid = threadIdx.x;
    const int lane = tid & 31, warp = tid >> 5;
    const int wm = warp & 3;        // 0..3 -> 64-row slice of 256
    const int wn = warp >> 2;       // 0..3 -> 32-col slice of 128
    const int m0 = blockIdx.y * BM;
    const int n0 = blockIdx.x * BN;
    constexpr int K = GELU ? EMB : FF;
    constexpr int Npar = GELU ? FF : EMB;
    constexpr int NC = K / BK;

    const __half* A = GELU ? g_Xh : g_H;
    const __half* B = GELU ? g_W1t : g_W2t;

    float* bias_s = reinterpret_cast<float*>(smem_raw + SM_BIAS);
    for (int i = tid; i < BN; i += TPB) bias_s[i] = bias[n0 + i];

    // ldmatrix lane -> row-offset / k-half mapping (validated R5/R7)
    const int a_roff = (lane & 7) + ((lane >> 3) & 1) * 8;
    const int a_hi   = (lane >> 4) & 1;
    const int b_noff = (lane & 7) + ((lane >> 4) & 1) * 8;
    const int b_hi   = (lane >> 3) & 1;

    // 64x32 warp tile: 4 m16 x 4 n8 -> 64 accumulators / thread
    float acc[4][4][4];
    #pragma unroll
    for (int mt = 0; mt < 4; mt++)
        #pragma unroll
        for (int nt = 0; nt < 4; nt++)
            #pragma unroll
            for (int e = 0; e < 4; e++) acc[mt][nt][e] = 0.f;

    // per-lane row byte offsets within a stage
    uint32_t a_rowb[4]; int a_rc[4];
    #pragma unroll
    for (int mt = 0; mt < 4; mt++) {
        int r = wm * 64 + mt * 16 + a_roff;
        a_rowb[mt] = r * 128; a_rc[mt] = r & 7;
    }
    uint32_t b_rowb[2]; int b_rc[2];
    #pragma unroll
    for (int p = 0; p < 2; p++) {
        int r = wn * 32 + p * 16 + b_noff;
        b_rowb[p] = r * 128; b_rc[p] = r & 7;
    }

    // prologue: 3 stages in flight
    load_tile(sb, 0, A, B, m0, n0, 0, K, tid);      CP_COMMIT();
    load_tile(sb, 1, A, B, m0, n0, BK, K, tid);     CP_COMMIT();
    load_tile(sb, 2, A, B, m0, n0, 2 * BK, K, tid); CP_COMMIT();

    for (int i = 0; i < NC; i++) {
        CP_WAIT2();           // chunk i's group complete
        __syncthreads();      // stage (i+3)&3 consumers from last iter are done
        uint32_t sa = sb + SM_TILES + (i & 3) * STG_BYTES;
        uint32_t sB = sa + A_BYTES;

        // kk=0 fragment loads first so prefetch issue cost is hidden
        uint32_t ar[4][4], br[2][4];
        #pragma unroll
        for (int mt = 0; mt < 4; mt++) {
            uint32_t ad = sa + a_rowb[mt] + ((a_hi ^ a_rc[mt]) << 4);
            LDSM4(ar[mt][0], ar[mt][1], ar[mt][2], ar[mt][3], ad);
        }
        #pragma unroll
        for (int p = 0; p < 2; p++) {
            uint32_t bd = sB + b_rowb[p] + ((b_hi ^ b_rc[p]) << 4);
            LDSM4(br[p][0], br[p][1], br[p][2], br[p][3], bd);
        }

        int pf = i + 3;
        if (pf < NC) load_tile(sb, pf & 3, A, B, m0, n0, pf * BK, K, tid);
        CP_COMMIT();

        #pragma unroll
        for (int kk = 0; kk < 4; kk++) {
            #pragma unroll
            for (int mt = 0; mt < 4; mt++)
                #pragma unroll
                for (int nt = 0; nt < 4; nt++) {
                    int p = nt >> 1, h = (nt & 1) << 1;
                    MMA16816(acc[mt][nt], ar[mt][0], ar[mt][1], ar[mt][2], ar[mt][3],
                             br[p][h], br[p][h + 1]);
                }
            if (kk < 3) {   // next k16 fragments
                int s = 2 * (kk + 1);
                #pragma unroll
                for (int mt = 0; mt < 4; mt++) {
                    uint32_t ad = sa + a_rowb[mt] + (((s + a_hi) ^ a_rc[mt]) << 4);
                    LDSM4(ar[mt][0], ar[mt][1], ar[mt][2], ar[mt][3], ad);
                }
                #pragma unroll
                for (int p = 0; p < 2; p++) {
                    uint32_t bd = sB + b_rowb[p] + (((s + b_hi) ^ b_rc[p]) << 4);
                    LDSM4(br[p][0], br[p][1], br[p][2], br[p][3], bd);
                }
            }
        }
    }

    // ---------------- epilogue: fragments -> bias (+GELU) -> global ----------------
    const int mrow = lane >> 2;            // 0..7
    const int ncol = (lane & 3) * 2;       // 0,2,4,6
    #pragma unroll
    for (int mt = 0; mt < 4; mt++) {
        #pragma unroll
        for (int nt = 0; nt < 4; nt++) {
            int col_l = wn * 32 + nt * 8 + ncol;
            float bi0 = bias_s[col_l], bi1 = bias_s[col_l + 1];
            #pragma unroll
            for (int half = 0; half < 2; half++) {   // d0d1 (m+0) / d2d3 (m+8)
                int row = m0 + wm * 64 + mt * 16 + mrow + half * 8;
                float v0 = acc[mt][nt][2 * half]     + bi0;
                float v1 = acc[mt][nt][2 * half + 1] + bi1;
                if (GELU) {
                    v0 = 0.5f * v0 * (1.0f + erff(v0 * 0.70710678118654752f));
                    v1 = 0.5f * v1 * (1.0f + erff(v1 * 0.70710678118654752f));
                }
                size_t off = (size_t)row * Npar + n0 + col_l;
                if (GELU) {
                    __half2 h2 = __floats2half2_rn(v0, v1);
                    *reinterpret_cast<__half2*>(g_H + off) = h2;
                } else {
                    float2 f2; f2.x = v0; f2.y = v1;
                    *reinterpret_cast<float2*>(out_f + off) = f2;
                }
            }
        }
    }
}

// ---------------- preprocessing (3 launches) ----------------
__global__ void absmean_both_k(const float4* __restrict__ W1,
                               const float4* __restrict__ W2) {
    __shared__ float sm[256];
    const int half = blockIdx.x >> 10;               // 0: W1, 1: W2
    const int blk = blockIdx.x & 1023;
    const float4* w = half ? W2 : W1;
    float s = 0.f;
    const int total = WN / 4;
    for (int i = blk * 256 + threadIdx.x; i < total; i += 1024 * 256) {
        float4 v = w[i];
        s += fabsf(v.x) + fabsf(v.y) + fabsf(v.z) + fabsf(v.w);
    }
    sm[threadIdx.x] = s;
    __syncthreads();
    #pragma unroll
    for (int d = 128; d > 0; d >>= 1) {
        if (threadIdx.x < d) sm[threadIdx.x] += sm[threadIdx.x + d];
        __syncthreads();
    }
    if (threadIdx.x == 0) g_partial[half * 1024 + blk] = sm[0];
}

__global__ void absmean_final_k() {
    __shared__ float sm[1024];
    sm[threadIdx.x] = g_partial[blockIdx.x * 1024 + threadIdx.x];
    __syncthreads();
    #pragma unroll
    for (int d = 512; d > 0; d >>= 1) {
        if (threadIdx.x < d) sm[threadIdx.x] += sm[threadIdx.x + d];
        __syncthreads();
    }
    if (threadIdx.x == 0) g_scale[blockIdx.x] = fmaxf(sm[0] / (float)WN, 1e-8f);
}

// one launch: quantize W1, W2 (ternary fp16) and convert x -> fp16
__global__ void prep_convert_k(const float4* __restrict__ W1,
                               const float4* __restrict__ W2,
                               const float4* __restrict__ x) {
    int i = blockIdx.x * 256 + threadIdx.x;
    const int Q = WN / 4;                    // 1M float4 per weight matrix
    uint2 u;
    if (i < 2 * Q) {
        int which = i >= Q;
        int j = i - which * Q;
        float inv = 1.0f / g_scale[which];
        float4 v = (which ? W2 : W1)[j];
        float a = fminf(fmaxf(rintf(v.x * inv), -1.f), 1.f);
        float b = fminf(fmaxf(rintf(v.y * inv), -1.f), 1.f);
        float c = fminf(fmaxf(rintf(v.z * inv), -1.f), 1.f);
        float d = fminf(fmaxf(rintf(v.w * inv), -1.f), 1.f);
        __half2 h0 = __floats2half2_rn(a, b);
        __half2 h1 = __floats2half2_rn(c, d);
        u.x = *reinterpret_cast<uint32_t*>(&h0);
        u.y = *reinterpret_cast<uint32_t*>(&h1);
        *reinterpret_cast<uint2*>((which ? g_W2t : g_W1t) + (size_t)j * 4) = u;
    } else {
        int j = i - 2 * Q;                  // 0 .. XN/4-1
        float4 v = x[j];
        __half2 h0 = __floats2half2_rn(v.x, v.y);
        __half2 h1 = __floats2half2_rn(v.z, v.w);
        u.x = *reinterpret_cast<uint32_t*>(&h0);
        u.y = *reinterpret_cast<uint32_t*>(&h1);
        *reinterpret_cast<uint2*>(g_Xh + (size_t)j * 4) = u;
    }
}

// ---------------- launcher ----------------
extern "C" void kernel_launch(void* const* d_in, const int* in_sizes, int n_in,
                              void* d_out, int out_size) {
    const float* x  = (const float*)d_in[0];
    const float* W1 = (const float*)d_in[1];
    const float* b1 = (const float*)d_in[2];
    const float* W2 = (const float*)d_in[3];
    const float* b2 = (const float*)d_in[4];
    float* out = (float*)d_out;

    cudaFuncSetAttribute(ffn_gemm<true>,  cudaFuncAttributeMaxDynamicSharedMemorySize, SMEM_TOTAL);
    cudaFuncSetAttribute(ffn_gemm<false>, cudaFuncAttributeMaxDynamicSharedMemorySize, SMEM_TOTAL);

    absmean_both_k<<<2048, 256>>>((const float4*)W1, (const float4*)W2);
    absmean_final_k<<<2, 1024>>>();
    prep_convert_k<<<(2 * (WN / 4) + XN / 4) / 256, 256>>>(
        (const float4*)W1, (const float4*)W2, (const float4*)x);

    ffn_gemm<true><<<dim3(FF / BN, NTOK / BM), TPB, SMEM_TOTAL>>>(b1, nullptr);
    ffn_gemm<false><<<dim3(EMB / BN, NTOK / BM), TPB, SMEM_TOTAL>>>(b2, out);
}

// round 9
// speedup vs baseline: 1.0113x; 1.0113x over previous
// BitNet-style FFN on GB300 — sm_103 baseline-ISA build (tcgen05 rejected by the
// harness's ptxas target). cp.async + ldmatrix + mma.sync.m16n8k16.f32.f16.f16.f32.
//   out = gelu_exact(x @ T(W1)^T + b1) @ T(W2)^T + b2,  T() = absmean ternary {-1,0,1}
// Ternary weights EXACT in fp16; x/H fp16, fp32 accumulators -> rel_err ~3e-4.
// R9: back to R7 shape (8 warps, 64x64 warp tile, BM=128/BN=256) but with
//     DOUBLE-BUFFERED fragments + interleaved LDSM/MMA issue. R7/R8 showed both
//     crossbar and tensor at ~54% because volatile-asm phase ordering serialized
//     them; interleaving overlaps the ~1500cyc/chunk LDSM stream under the
//     ~2048cyc/chunk MMA stream.

#include <cuda_runtime.h>
#include <cuda_fp16.h>
#include <cstdint>

#define EMB 1024
#define FF 4096
#define NTOK 8192
#define WN (FF * EMB)
#define XN (NTOK * EMB)

// ---------------- device-global scratch (allocation-free rule) ----------------
__device__ __align__(16) __half g_Xh[(size_t)NTOK * EMB];   // 16 MB
__device__ __align__(16) __half g_W1t[(size_t)FF * EMB];    // 8 MB
__device__ __align__(16) __half g_W2t[(size_t)FF * EMB];    // 8 MB
__device__ __align__(16) __half g_H[(size_t)NTOK * FF];     // 64 MB
__device__ float g_partial[2048];
__device__ float g_scale[2];

// ---------------- PTX helpers (baseline ISA only) ----------------
__device__ __forceinline__ uint32_t smem_u32(const void* p) {
    uint32_t a;
    asm("{ .reg .u64 t; cvta.to.shared.u64 t, %1; cvt.u32.u64 %0, t; }" : "=r"(a) : "l"(p));
    return a;
}

#define CP16(dst, src) \
    asm volatile("cp.async.cg.shared.global [%0], [%1], 16;" \
                 :: "r"((uint32_t)(dst)), "l"(__cvta_generic_to_global(src)) : "memory")
#define CP_COMMIT()  asm volatile("cp.async.commit_group;" ::: "memory")
#define CP_WAIT2()   asm volatile("cp.async.wait_group 2;" ::: "memory")

#define LDSM4(r0, r1, r2, r3, addr) \
    asm volatile("ldmatrix.sync.aligned.m8n8.x4.shared.b16 {%0,%1,%2,%3}, [%4];" \
                 : "=r"(r0), "=r"(r1), "=r"(r2), "=r"(r3) : "r"(addr))

#define MMA16816(d, a0, a1, a2, a3, b0, b1) \
    asm volatile("mma.sync.aligned.m16n8k16.row.col.f32.f16.f16.f32 " \
                 "{%0,%1,%2,%3}, {%4,%5,%6,%7}, {%8,%9}, {%0,%1,%2,%3};" \
                 : "+f"((d)[0]), "+f"((d)[1]), "+f"((d)[2]), "+f"((d)[3]) \
                 : "r"(a0), "r"(a1), "r"(a2), "r"(a3), "r"(b0), "r"(b1))

// ---------------- GEMM configuration ----------------
constexpr int BM = 128, BN = 256, BK = 64, NST = 4, TPB = 256;
constexpr int A_BYTES = BM * 128;            // 16 KB
constexpr int B_BYTES = BN * 128;            // 32 KB
constexpr int STG_BYTES = A_BYTES + B_BYTES; // 48 KB
constexpr int SM_BIAS = 0, SM_TILES = 2048;
constexpr int SMEM_TOTAL = SM_TILES + NST * STG_BYTES;   // 198656 B

// Per-stage tile loader. A and B both K-major, 64 halves (= 8 x 16B segs) per row.
// SW128 swizzle: seg' = seg ^ (row & 7) -> conflict-free cp.async + ldmatrix.
__device__ __forceinline__ void load_tile(uint32_t sb, int stage,
                                          const __half* __restrict__ A,
                                          const __half* __restrict__ B,
                                          int m0, int n0, int kc, int K, int tid) {
    uint32_t sa = sb + SM_TILES + stage * STG_BYTES;
    uint32_t sB = sa + A_BYTES;
    #pragma unroll
    for (int t = 0; t < 4; t++) {            // A: 128 rows x 8 segs = 1024 chunks
        int i = tid + t * TPB;
        int r = i >> 3, s = i & 7;
        uint32_t dst = sa + r * 128 + ((s ^ (r & 7)) << 4);
        CP16(dst, A + (size_t)(m0 + r) * K + kc + s * 8);
    }
    #pragma unroll
    for (int t = 0; t < 8; t++) {            // B: 256 rows x 8 segs = 2048 chunks
        int i = tid + t * TPB;
        int r = i >> 3, s = i & 7;
        uint32_t dst = sB + r * 128 + ((s ^ (r & 7)) << 4);
        CP16(dst, B + (size_t)(n0 + r) * K + kc + s * 8);
    }
}

// ---------------- fused GEMM + epilogue ----------------
// GELU=true : A=g_Xh [8192,1024], B=g_W1t [4096,1024], out=g_H (fp16), +b1, erf-GELU
// GELU=false: A=g_H  [8192,4096], B=g_W2t [1024,4096], out=out_f (fp32), +b2
template <bool GELU>
__global__ void __launch_bounds__(TPB)
ffn_gemm(const float* __restrict__ bias, float* __restrict__ out_f) {
    extern __shared__ __align__(1024) uint8_t smem_raw[];
    uint32_t sb = smem_u32(smem_raw);
    const int tid = threadIdx.x;
    const int lane = tid & 31, warp = tid >> 5;
    const int wm = warp & 1;        // 0..1 -> 64-row slice
    const int wn = warp >> 1;       // 0..3 -> 64-col slice
    const int m0 = blockIdx.y * BM;
    const int n0 = blockIdx.x * BN;
    constexpr int K = GELU ? EMB : FF;
    constexpr int Npar = GELU ? FF : EMB;
    constexpr int NC = K / BK;

    const __half* A = GELU ? g_Xh : g_H;
    const __half* B = GELU ? g_W1t : g_W2t;

    float* bias_s = reinterpret_cast<float*>(smem_raw + SM_BIAS);
    for (int i = tid; i < BN; i += TPB) bias_s[i] = bias[n0 + i];

    // ldmatrix lane -> row-offset / k-half mapping (validated R5/R7)
    const int a_roff = (lane & 7) + ((lane >> 3) & 1) * 8;
    const int a_hi   = (lane >> 4) & 1;
    const int b_noff = (lane & 7) + ((lane >> 4) & 1) * 8;
    const int b_hi   = (lane >> 3) & 1;

    // 64x64 warp tile: 4 m16 x 8 n8 -> 128 accumulators / thread
    float acc[4][8][4];
    #pragma unroll
    for (int mt = 0; mt < 4; mt++)
        #pragma unroll
        for (int nt = 0; nt < 8; nt++)
            #pragma unroll
            for (int e = 0; e < 4; e++) acc[mt][nt][e] = 0.f;

    // per-lane row byte offsets within a stage
    uint32_t a_rowb[4]; int a_rc[4];
    #pragma unroll
    for (int mt = 0; mt < 4; mt++) {
        int r = wm * 64 + mt * 16 + a_roff;
        a_rowb[mt] = r * 128; a_rc[mt] = r & 7;
    }
    uint32_t b_rowb[4]; int b_rc[4];
    #pragma unroll
    for (int p = 0; p < 4; p++) {
        int r = wn * 64 + p * 16 + b_noff;
        b_rowb[p] = r * 128; b_rc[p] = r & 7;
    }

    // double-buffered fragments
    uint32_t ar[2][4][4], br[2][4][4];

    // prologue: 3 stages in flight; group 0 retired before first read
    load_tile(sb, 0, A, B, m0, n0, 0, K, tid);      CP_COMMIT();
    load_tile(sb, 1, A, B, m0, n0, BK, K, tid);     CP_COMMIT();
    load_tile(sb, 2, A, B, m0, n0, 2 * BK, K, tid); CP_COMMIT();
    CP_WAIT2();   // group 0 complete (pending: 1,2)

    for (int i = 0; i < NC; i++) {
        // barrier: (a) pairs with end-of-iter CP_WAIT2 so stage i's data (written
        // by ALL threads' groups) is visible; (b) protects stage (i+3)&3 reuse.
        __syncthreads();
        uint32_t sa = sb + SM_TILES + (i & 3) * STG_BYTES;
        uint32_t sB = sa + A_BYTES;

        int pf = i + 3;
        if (pf < NC) load_tile(sb, pf & 3, A, B, m0, n0, pf * BK, K, tid);
        CP_COMMIT();

        // kk=0 fragments -> buf 0
        #pragma unroll
        for (int mt = 0; mt < 4; mt++) {
            uint32_t ad = sa + a_rowb[mt] + ((a_hi ^ a_rc[mt]) << 4);
            LDSM4(ar[0][mt][0], ar[0][mt][1], ar[0][mt][2], ar[0][mt][3], ad);
        }
        #pragma unroll
        for (int p = 0; p < 4; p++) {
            uint32_t bd = sB + b_rowb[p] + ((b_hi ^ b_rc[p]) << 4);
            LDSM4(br[0][p][0], br[0][p][1], br[0][p][2], br[0][p][3], bd);
        }

        // phases: MMA(buf kk&1) with next phase's LDSM interleaved (volatile
        // order IS issue order — this is the overlap R7/R8 lacked)
        #pragma unroll
        for (int kk = 0; kk < 4; kk++) {
            const int cb = kk & 1, nb = cb ^ 1;
            const int s = 2 * (kk + 1);
            #pragma unroll
            for (int mt = 0; mt < 4; mt++) {
                if (kk < 3) {   // 2 LDSM ahead of each 8-MMA section
                    uint32_t ad = sa + a_rowb[mt] + (((s + a_hi) ^ a_rc[mt]) << 4);
                    LDSM4(ar[nb][mt][0], ar[nb][mt][1], ar[nb][mt][2], ar[nb][mt][3], ad);
                    uint32_t bd = sB + b_rowb[mt] + (((s + b_hi) ^ b_rc[mt]) << 4);
                    LDSM4(br[nb][mt][0], br[nb][mt][1], br[nb][mt][2], br[nb][mt][3], bd);
                }
                #pragma unroll
                for (int nt = 0; nt < 8; nt++) {
                    int p = nt >> 1, h = (nt & 1) << 1;
                    MMA16816(acc[mt][nt],
                             ar[cb][mt][0], ar[cb][mt][1], ar[cb][mt][2], ar[cb][mt][3],
                             br[cb][p][h], br[cb][p][h + 1]);
                }
            }
        }
        // retire group i+1 so next iter's barrier+reads are safe
        CP_WAIT2();
    }

    // ---------------- epilogue: fragments -> bias (+GELU) -> global ----------------
    const int mrow = lane >> 2;            // 0..7
    const int ncol = (lane & 3) * 2;       // 0,2,4,6
    #pragma unroll
    for (int mt = 0; mt < 4; mt++) {
        #pragma unroll
        for (int nt = 0; nt < 8; nt++) {
            int col_l = wn * 64 + nt * 8 + ncol;
            float bi0 = bias_s[col_l], bi1 = bias_s[col_l + 1];
            #pragma unroll
            for (int half = 0; half < 2; half++) {   // d0d1 (m+0) / d2d3 (m+8)
                int row = m0 + wm * 64 + mt * 16 + mrow + half * 8;
                float v0 = acc[mt][nt][2 * half]     + bi0;
                float v1 = acc[mt][nt][2 * half + 1] + bi1;
                if (GELU) {
                    v0 = 0.5f * v0 * (1.0f + erff(v0 * 0.70710678118654752f));
                    v1 = 0.5f * v1 * (1.0f + erff(v1 * 0.70710678118654752f));
                }
                size_t off = (size_t)row * Npar + n0 + col_l;
                if (GELU) {
                    __half2 h2 = __floats2half2_rn(v0, v1);
                    *reinterpret_cast<__half2*>(g_H + off) = h2;
                } else {
                    float2 f2; f2.x = v0; f2.y = v1;
                    *reinterpret_cast<float2*>(out_f + off) = f2;
                }
            }
        }
    }
}

// ---------------- preprocessing (3 launches) ----------------
__global__ void absmean_both_k(const float4* __restrict__ W1,
                               const float4* __restrict__ W2) {
    __shared__ float sm[256];
    const int half = blockIdx.x >> 10;               // 0: W1, 1: W2
    const int blk = blockIdx.x & 1023;
    const float4* w = half ? W2 : W1;
    float s = 0.f;
    const int total = WN / 4;
    for (int i = blk * 256 + threadIdx.x; i < total; i += 1024 * 256) {
        float4 v = w[i];
        s += fabsf(v.x) + fabsf(v.y) + fabsf(v.z) + fabsf(v.w);
    }
    sm[threadIdx.x] = s;
    __syncthreads();
    #pragma unroll
    for (int d = 128; d > 0; d >>= 1) {
        if (threadIdx.x < d) sm[threadIdx.x] += sm[threadIdx.x + d];
        __syncthreads();
    }
    if (threadIdx.x == 0) g_partial[half * 1024 + blk] = sm[0];
}

__global__ void absmean_final_k() {
    __shared__ float sm[1024];
    sm[threadIdx.x] = g_partial[blockIdx.x * 1024 + threadIdx.x];
    __syncthreads();
    #pragma unroll
    for (int d = 512; d > 0; d >>= 1) {
        if (threadIdx.x < d) sm[threadIdx.x] += sm[threadIdx.x + d];
        __syncthreads();
    }
    if (threadIdx.x == 0) g_scale[blockIdx.x] = fmaxf(sm[0] / (float)WN, 1e-8f);
}

// one launch: quantize W1, W2 (ternary fp16) and convert x -> fp16
__global__ void prep_convert_k(const float4* __restrict__ W1,
                               const float4* __restrict__ W2,
                               const float4* __restrict__ x) {
    int i = blockIdx.x * 256 + threadIdx.x;
    const int Q = WN / 4;                    // 1M float4 per weight matrix
    uint2 u;
    if (i < 2 * Q) {
        int which = i >= Q;
        int j = i - which * Q;
        float inv = 1.0f / g_scale[which];
        float4 v = (which ? W2 : W1)[j];
        float a = fminf(fmaxf(rintf(v.x * inv), -1.f), 1.f);
        float b = fminf(fmaxf(rintf(v.y * inv), -1.f), 1.f);
        float c = fminf(fmaxf(rintf(v.z * inv), -1.f), 1.f);
        float d = fminf(fmaxf(rintf(v.w * inv), -1.f), 1.f);
        __half2 h0 = __floats2half2_rn(a, b);
        __half2 h1 = __floats2half2_rn(c, d);
        u.x = *reinterpret_cast<uint32_t*>(&h0);
        u.y = *reinterpret_cast<uint32_t*>(&h1);
        *reinterpret_cast<uint2*>((which ? g_W2t : g_W1t) + (size_t)j * 4) = u;
    } else {
        int j = i - 2 * Q;                  // 0 .. XN/4-1
        float4 v = x[j];
        __half2 h0 = __floats2half2_rn(v.x, v.y);
        __half2 h1 = __floats2half2_rn(v.z, v.w);
        u.x = *reinterpret_cast<uint32_t*>(&h0);
        u.y = *reinterpret_cast<uint32_t*>(&h1);
        *reinterpret_cast<uint2*>(g_Xh + (size_t)j * 4) = u;
    }
}

// ---------------- launcher ----------------
extern "C" void kernel_launch(void* const* d_in, const int* in_sizes, int n_in,
                              void* d_out, int out_size) {
    const float* x  = (const float*)d_in[0];
    const float* W1 = (const float*)d_in[1];
    const float* b1 = (const float*)d_in[2];
    const float* W2 = (const float*)d_in[3];
    const float* b2 = (const float*)d_in[4];
    float* out = (float*)d_out;

    cudaFuncSetAttribute(ffn_gemm<true>,  cudaFuncAttributeMaxDynamicSharedMemorySize, SMEM_TOTAL);
    cudaFuncSetAttribute(ffn_gemm<false>, cudaFuncAttributeMaxDynamicSharedMemorySize, SMEM_TOTAL);

    absmean_both_k<<<2048, 256>>>((const float4*)W1, (const float4*)W2);
    absmean_final_k<<<2, 1024>>>();
    prep_convert_k<<<(2 * (WN / 4) + XN / 4) / 256, 256>>>(
        (const float4*)W1, (const float4*)W2, (const float4*)x);

    ffn_gemm<true><<<dim3(FF / BN, NTOK / BM), TPB, SMEM_TOTAL>>>(b1, nullptr);
    ffn_gemm<false><<<dim3(EMB / BN, NTOK / BM), TPB, SMEM_TOTAL>>>(b2, out);
}

// round 10
// speedup vs baseline: 1.0263x; 1.0149x over previous
// BitNet-style FFN on GB300 — sm_103 baseline-ISA build (tcgen05 rejected by the
// harness's ptxas target). cp.async + ldmatrix + mma.sync.m16n8k16.f32.f16.f16.f32.
//   out = gelu_exact(x @ T(W1)^T + b1) @ T(W2)^T + b2,  T() = absmean ternary {-1,0,1}
// Ternary weights EXACT in fp16; x/H fp16, fp32 accumulators -> rel_err ~3e-4.
// R10: (1) MMA asm is now NON-volatile — R7/R8/R9 all pinned at 14.4 cyc/MMA/SMSP
//      with volatile MMAs freezing issue order; ptxas can now software-pipeline
//      MMAs across LDSM bursts/prefetch. (2) templated tiles: GEMM2 64x128
//      (1024 CTAs, ~1% tail vs 15% at 1.73 waves before).

#include <cuda_runtime.h>
#include <cuda_fp16.h>
#include <cstdint>

#define EMB 1024
#define FF 4096
#define NTOK 8192
#define WN_ (FF * EMB)
#define XN_ (NTOK * EMB)

// ---------------- device-global scratch (allocation-free rule) ----------------
__device__ __align__(16) __half g_Xh[(size_t)NTOK * EMB];   // 16 MB
__device__ __align__(16) __half g_W1t[(size_t)FF * EMB];    // 8 MB
__device__ __align__(16) __half g_W2t[(size_t)FF * EMB];    // 8 MB
__device__ __align__(16) __half g_H[(size_t)NTOK * FF];     // 64 MB
__device__ float g_partial[2048];
__device__ float g_scale[2];

// ---------------- PTX helpers ----------------
__device__ __forceinline__ uint32_t smem_u32(const void* p) {
    uint32_t a;
    asm("{ .reg .u64 t; cvta.to.shared.u64 t, %1; cvt.u32.u64 %0, t; }" : "=r"(a) : "l"(p));
    return a;
}

#define CP16(dst, src) \
    asm volatile("cp.async.cg.shared.global [%0], [%1], 16;" \
                 :: "r"((uint32_t)(dst)), "l"(__cvta_generic_to_global(src)) : "memory")
#define CP_COMMIT()  asm volatile("cp.async.commit_group;" ::: "memory")
#define CP_WAIT2()   asm volatile("cp.async.wait_group 2;" ::: "memory")

// LDSM stays volatile: its ordering vs cp.async writes + barriers must hold.
#define LDSM4(r0, r1, r2, r3, addr) \
    asm volatile("ldmatrix.sync.aligned.m8n8.x4.shared.b16 {%0,%1,%2,%3}, [%4];" \
                 : "=r"(r0), "=r"(r1), "=r"(r2), "=r"(r3) : "r"(addr))

// MMA non-volatile: fully register-described; lets ptxas schedule/pipeline.
#define MMA16816(d, a0, a1, a2, a3, b0, b1) \
    asm("mma.sync.aligned.m16n8k16.row.col.f32.f16.f16.f32 " \
        "{%0,%1,%2,%3}, {%4,%5,%6,%7}, {%8,%9}, {%0,%1,%2,%3};" \
        : "+f"((d)[0]), "+f"((d)[1]), "+f"((d)[2]), "+f"((d)[3]) \
        : "r"(a0), "r"(a1), "r"(a2), "r"(a3), "r"(b0), "r"(b1))

constexpr int NST = 4;

// ---------------- fused GEMM + epilogue (templated tiles) ----------------
// GELU=true : A=g_Xh [8192,1024], B=g_W1t [4096,1024], out=g_H (fp16), +b1, erf-GELU
// GELU=false: A=g_H  [8192,4096], B=g_W2t [1024,4096], out=out_f (fp32), +b2
template <int BM, int BN, int WM, int WN, bool GELU>
__global__ void __launch_bounds__((BM / WM) * (BN / WN) * 32)
ffn_gemm(const float* __restrict__ bias, float* __restrict__ out_f) {
    constexpr int TPB = (BM / WM) * (BN / WN) * 32;
    constexpr int A_BYTES = BM * 128;
    constexpr int B_BYTES = BN * 128;
    constexpr int STG_BYTES = A_BYTES + B_BYTES;
    constexpr int SM_TILES = 2048;
    constexpr int MT = WM / 16;     // A m16 tiles per warp
    constexpr int PT = WN / 16;     // B ldsm tiles per warp
    constexpr int NT = WN / 8;      // n8 tiles per warp
    constexpr int MW_CNT = BM / WM;
    constexpr int K = GELU ? EMB : FF;
    constexpr int Npar = GELU ? FF : EMB;
    constexpr int NC = K / 64;

    extern __shared__ __align__(1024) uint8_t smem_raw[];
    uint32_t sb = smem_u32(smem_raw);
    const int tid = threadIdx.x;
    const int lane = tid & 31, warp = tid >> 5;
    const int wm = warp % MW_CNT;
    const int wn = warp / MW_CNT;
    const int m0 = blockIdx.y * BM;
    const int n0 = blockIdx.x * BN;

    const __half* A = GELU ? g_Xh : g_H;
    const __half* B = GELU ? g_W1t : g_W2t;

    float* bias_s = reinterpret_cast<float*>(smem_raw);
    for (int i = tid; i < BN; i += TPB) bias_s[i] = bias[n0 + i];

    // ldmatrix lane -> row-offset / k-half mapping (validated R5/R7)
    const int a_roff = (lane & 7) + ((lane >> 3) & 1) * 8;
    const int a_hi   = (lane >> 4) & 1;
    const int b_noff = (lane & 7) + ((lane >> 4) & 1) * 8;
    const int b_hi   = (lane >> 3) & 1;

    float acc[MT][NT][4];
    #pragma unroll
    for (int mt = 0; mt < MT; mt++)
        #pragma unroll
        for (int nt = 0; nt < NT; nt++)
            #pragma unroll
            for (int e = 0; e < 4; e++) acc[mt][nt][e] = 0.f;

    uint32_t a_rowb[MT]; int a_rc[MT];
    #pragma unroll
    for (int mt = 0; mt < MT; mt++) {
        int r = wm * WM + mt * 16 + a_roff;
        a_rowb[mt] = r * 128; a_rc[mt] = r & 7;
    }
    uint32_t b_rowb[PT]; int b_rc[PT];
    #pragma unroll
    for (int p = 0; p < PT; p++) {
        int r = wn * WN + p * 16 + b_noff;
        b_rowb[p] = r * 128; b_rc[p] = r & 7;
    }

    // per-stage tile loader (SW128 swizzle, conflict-free)
    auto load_tile = [&](int stage, int kc) {
        uint32_t sa = sb + SM_TILES + stage * STG_BYTES;
        uint32_t sB = sa + A_BYTES;
        #pragma unroll
        for (int t = 0; t < BM * 8 / TPB; t++) {
            int i = tid + t * TPB;
            int r = i >> 3, s = i & 7;
            uint32_t dst = sa + r * 128 + ((s ^ (r & 7)) << 4);
            CP16(dst, A + (size_t)(m0 + r) * K + kc + s * 8);
        }
        #pragma unroll
        for (int t = 0; t < BN * 8 / TPB; t++) {
            int i = tid + t * TPB;
            int r = i >> 3, s = i & 7;
            uint32_t dst = sB + r * 128 + ((s ^ (r & 7)) << 4);
            CP16(dst, B + (size_t)(n0 + r) * K + kc + s * 8);
        }
    };

    uint32_t ar[2][MT][4], br[2][PT][4];

    // prologue: 3 stages in flight; group 0 retired before first read
    load_tile(0, 0);      CP_COMMIT();
    load_tile(1, 64);     CP_COMMIT();
    load_tile(2, 128);    CP_COMMIT();
    CP_WAIT2();

    for (int i = 0; i < NC; i++) {
        __syncthreads();   // stage i data visible; stage (i+3)&3 free for reuse
        uint32_t sa = sb + SM_TILES + (i & 3) * STG_BYTES;
        uint32_t sB = sa + A_BYTES;

        int pf = i + 3;
        if (pf < NC) load_tile(pf & 3, pf * 64);
        CP_COMMIT();

        // kk=0 fragments -> buf 0
        #pragma unroll
        for (int mt = 0; mt < MT; mt++) {
            uint32_t ad = sa + a_rowb[mt] + ((a_hi ^ a_rc[mt]) << 4);
            LDSM4(ar[0][mt][0], ar[0][mt][1], ar[0][mt][2], ar[0][mt][3], ad);
        }
        #pragma unroll
        for (int p = 0; p < PT; p++) {
            uint32_t bd = sB + b_rowb[p] + ((b_hi ^ b_rc[p]) << 4);
            LDSM4(br[0][p][0], br[0][p][1], br[0][p][2], br[0][p][3], bd);
        }

        #pragma unroll
        for (int kk = 0; kk < 4; kk++) {
            const int cb = kk & 1, nb = cb ^ 1;
            if (kk < 3) {    // next-phase fragments; ptxas interleaves MMAs freely
                const int s = 2 * (kk + 1);
                #pragma unroll
                for (int mt = 0; mt < MT; mt++) {
                    uint32_t ad = sa + a_rowb[mt] + (((s + a_hi) ^ a_rc[mt]) << 4);
                    LDSM4(ar[nb][mt][0], ar[nb][mt][1], ar[nb][mt][2], ar[nb][mt][3], ad);
                }
                #pragma unroll
                for (int p = 0; p < PT; p++) {
                    uint32_t bd = sB + b_rowb[p] + (((s + b_hi) ^ b_rc[p]) << 4);
                    LDSM4(br[nb][p][0], br[nb][p][1], br[nb][p][2], br[nb][p][3], bd);
                }
            }
            #pragma unroll
            for (int mt = 0; mt < MT; mt++)
                #pragma unroll
                for (int nt = 0; nt < NT; nt++) {
                    int p = nt >> 1, h = (nt & 1) << 1;
                    MMA16816(acc[mt][nt],
                             ar[cb][mt][0], ar[cb][mt][1], ar[cb][mt][2], ar[cb][mt][3],
                             br[cb][p][h], br[cb][p][h + 1]);
                }
        }
        CP_WAIT2();   // retire group i+1 for next iter
    }

    // ---------------- epilogue: fragments -> bias (+GELU) -> global ----------------
    const int mrow = lane >> 2;            // 0..7
    const int ncol = (lane & 3) * 2;       // 0,2,4,6
    #pragma unroll
    for (int mt = 0; mt < MT; mt++) {
        #pragma unroll
        for (int nt = 0; nt < NT; nt++) {
            int col_l = wn * WN + nt * 8 + ncol;
            float bi0 = bias_s[col_l], bi1 = bias_s[col_l + 1];
            #pragma unroll
            for (int half = 0; half < 2; half++) {   // d0d1 (m+0) / d2d3 (m+8)
                int row = m0 + wm * WM + mt * 16 + mrow + half * 8;
                float v0 = acc[mt][nt][2 * half]     + bi0;
                float v1 = acc[mt][nt][2 * half + 1] + bi1;
                if (GELU) {
                    v0 = 0.5f * v0 * (1.0f + erff(v0 * 0.70710678118654752f));
                    v1 = 0.5f * v1 * (1.0f + erff(v1 * 0.70710678118654752f));
                }
                size_t off = (size_t)row * Npar + n0 + col_l;
                if (GELU) {
                    __half2 h2 = __floats2half2_rn(v0, v1);
                    *reinterpret_cast<__half2*>(g_H + off) = h2;
                } else {
                    float2 f2; f2.x = v0; f2.y = v1;
                    *reinterpret_cast<float2*>(out_f + off) = f2;
                }
            }
        }
    }
}

// ---------------- preprocessing (3 launches) ----------------
__global__ void absmean_both_k(const float4* __restrict__ W1,
                               const float4* __restrict__ W2) {
    __shared__ float sm[256];
    const int half = blockIdx.x >> 10;               // 0: W1, 1: W2
    const int blk = blockIdx.x & 1023;
    const float4* w = half ? W2 : W1;
    float s = 0.f;
    const int total = WN_ / 4;
    for (int i = blk * 256 + threadIdx.x; i < total; i += 1024 * 256) {
        float4 v = w[i];
        s += fabsf(v.x) + fabsf(v.y) + fabsf(v.z) + fabsf(v.w);
    }
    sm[threadIdx.x] = s;
    __syncthreads();
    #pragma unroll
    for (int d = 128; d > 0; d >>= 1) {
        if (threadIdx.x < d) sm[threadIdx.x] += sm[threadIdx.x + d];
        __syncthreads();
    }
    if (threadIdx.x == 0) g_partial[half * 1024 + blk] = sm[0];
}

__global__ void absmean_final_k() {
    __shared__ float sm[1024];
    sm[threadIdx.x] = g_partial[blockIdx.x * 1024 + threadIdx.x];
    __syncthreads();
    #pragma unroll
    for (int d = 512; d > 0; d >>= 1) {
        if (threadIdx.x < d) sm[threadIdx.x] += sm[threadIdx.x + d];
        __syncthreads();
    }
    if (threadIdx.x == 0) g_scale[blockIdx.x] = fmaxf(sm[0] / (float)WN_, 1e-8f);
}

// one launch: quantize W1, W2 (ternary fp16) and convert x -> fp16
__global__ void prep_convert_k(const float4* __restrict__ W1,
                               const float4* __restrict__ W2,
                               const float4* __restrict__ x) {
    int i = blockIdx.x * 256 + threadIdx.x;
    const int Q = WN_ / 4;                   // 1M float4 per weight matrix
    uint2 u;
    if (i < 2 * Q) {
        int which = i >= Q;
        int j = i - which * Q;
        float inv = 1.0f / g_scale[which];
        float4 v = (which ? W2 : W1)[j];
        float a = fminf(fmaxf(rintf(v.x * inv), -1.f), 1.f);
        float b = fminf(fmaxf(rintf(v.y * inv), -1.f), 1.f);
        float c = fminf(fmaxf(rintf(v.z * inv), -1.f), 1.f);
        float d = fminf(fmaxf(rintf(v.w * inv), -1.f), 1.f);
        __half2 h0 = __floats2half2_rn(a, b);
        __half2 h1 = __floats2half2_rn(c, d);
        u.x = *reinterpret_cast<uint32_t*>(&h0);
        u.y = *reinterpret_cast<uint32_t*>(&h1);
        *reinterpret_cast<uint2*>((which ? g_W2t : g_W1t) + (size_t)j * 4) = u;
    } else {
        int j = i - 2 * Q;                  // 0 .. XN/4-1
        float4 v = x[j];
        __half2 h0 = __floats2half2_rn(v.x, v.y);
        __half2 h1 = __floats2half2_rn(v.z, v.w);
        u.x = *reinterpret_cast<uint32_t*>(&h0);
        u.y = *reinterpret_cast<uint32_t*>(&h1);
        *reinterpret_cast<uint2*>(g_Xh + (size_t)j * 4) = u;
    }
}

// ---------------- launcher ----------------
extern "C" void kernel_launch(void* const* d_in, const int* in_sizes, int n_in,
                              void* d_out, int out_size) {
    const float* x  = (const float*)d_in[0];
    const float* W1 = (const float*)d_in[1];
    const float* b1 = (const float*)d_in[2];
    const float* W2 = (const float*)d_in[3];
    const float* b2 = (const float*)d_in[4];
    float* out = (float*)d_out;

    // GEMM1: 128x256 tiles, 64x64 warps (8 warps), grid 16x64 = 1024 CTAs
    constexpr int SM1 = 2048 + NST * (128 * 128 + 256 * 128);   // 198656
    // GEMM2: 64x128 tiles, 32x32 warps (8 warps), grid 8x128 = 1024 CTAs
    constexpr int SM2 = 2048 + NST * (64 * 128 + 128 * 128);    // 100352

    cudaFuncSetAttribute((const void*)ffn_gemm<128, 256, 64, 64, true>,
                         cudaFuncAttributeMaxDynamicSharedMemorySize, SM1);
    cudaFuncSetAttribute((const void*)ffn_gemm<64, 128, 32, 32, false>,
                         cudaFuncAttributeMaxDynamicSharedMemorySize, SM2);

    absmean_both_k<<<2048, 256>>>((const float4*)W1, (const float4*)W2);
    absmean_final_k<<<2, 1024>>>();
    prep_convert_k<<<(2 * (WN_ / 4) + XN_ / 4) / 256, 256>>>(
        (const float4*)W1, (const float4*)W2, (const float4*)x);

    ffn_gemm<128, 256, 64, 64, true>
        <<<dim3(FF / 256, NTOK / 128), 256, SM1>>>(b1, nullptr);
    ffn_gemm<64, 128, 32, 32, false>
        <<<dim3(EMB / 128, NTOK / 64), 256, SM2>>>(b2, out);
}

// round 11
// speedup vs baseline: 1.0273x; 1.0010x over previous
// BitNet-style FFN on GB300 — sm_103 baseline-ISA build (tcgen05 rejected by the
// harness's ptxas). cp.async + ldmatrix + mma.sync.m16n8k16.
//   out = gelu_exact(x @ T(W1)^T + b1) @ T(W2)^T + b2,  T() = absmean ternary {-1,0,1}
// R11 experiments (attributable per-kernel):
//   (1) BK=128 two-stage pipeline (was BK=64 x 4): halves chunk count -> halves
//       per-chunk overhead (barrier + wait + kk0-LDSM exposure). GEMM1 8 chunks,
//       GEMM2 32 chunks.
//   (2) GEMM1 uses f16-ACCUM MMA (possible 2x rate on Blackwell legacy pipe) with
//       f32 promotion once per BK=128 chunk: rel_err model ~6.6e-4 < 1e-3.

#include <cuda_runtime.h>
#include <cuda_fp16.h>
#include <cstdint>

#define EMB 1024
#define FF 4096
#define NTOK 8192
#define WN_ (FF * EMB)
#define XN_ (NTOK * EMB)

// ---------------- device-global scratch (allocation-free rule) ----------------
__device__ __align__(16) __half g_Xh[(size_t)NTOK * EMB];   // 16 MB
__device__ __align__(16) __half g_W1t[(size_t)FF * EMB];    // 8 MB
__device__ __align__(16) __half g_W2t[(size_t)FF * EMB];    // 8 MB
__device__ __align__(16) __half g_H[(size_t)NTOK * FF];     // 64 MB
__device__ float g_partial[2048];
__device__ float g_scale[2];

// ---------------- PTX helpers ----------------
__device__ __forceinline__ uint32_t smem_u32(const void* p) {
    uint32_t a;
    asm("{ .reg .u64 t; cvta.to.shared.u64 t, %1; cvt.u32.u64 %0, t; }" : "=r"(a) : "l"(p));
    return a;
}

#define CP16(dst, src) \
    asm volatile("cp.async.cg.shared.global [%0], [%1], 16;" \
                 :: "r"((uint32_t)(dst)), "l"(__cvta_generic_to_global(src)) : "memory")
#define CP_COMMIT()  asm volatile("cp.async.commit_group;" ::: "memory")
#define CP_WAIT1()   asm volatile("cp.async.wait_group 1;" ::: "memory")

#define LDSM4(r0, r1, r2, r3, addr) \
    asm volatile("ldmatrix.sync.aligned.m8n8.x4.shared.b16 {%0,%1,%2,%3}, [%4];" \
                 : "=r"(r0), "=r"(r1), "=r"(r2), "=r"(r3) : "r"(addr))

// f32-accumulate MMA (GEMM2)
#define MMA16816F(d, a0, a1, a2, a3, b0, b1) \
    asm("mma.sync.aligned.m16n8k16.row.col.f32.f16.f16.f32 " \
        "{%0,%1,%2,%3}, {%4,%5,%6,%7}, {%8,%9}, {%0,%1,%2,%3};" \
        : "+f"((d)[0]), "+f"((d)[1]), "+f"((d)[2]), "+f"((d)[3]) \
        : "r"(a0), "r"(a1), "r"(a2), "r"(a3), "r"(b0), "r"(b1))

// f16-accumulate MMA (GEMM1 experiment): D/C = 2 b32 regs (4 halves)
#define MMA16816H(dh, a0, a1, a2, a3, b0, b1) \
    asm("mma.sync.aligned.m16n8k16.row.col.f16.f16.f16.f16 " \
        "{%0,%1}, {%2,%3,%4,%5}, {%6,%7}, {%0,%1};" \
        : "+r"((dh)[0]), "+r"((dh)[1]) \
        : "r"(a0), "r"(a1), "r"(a2), "r"(a3), "r"(b0), "r"(b1))

// ---------------- fused GEMM + epilogue ----------------
// BK = 128 (16 segs of 16B per row), 2 smem stages, 8 warps of 64x64.
// FACC16: use f16-accum MMA with once-per-chunk f32 promotion.
template <int BM, int BN, bool GELU, bool FACC16>
__global__ void __launch_bounds__(256)
ffn_gemm(const float* __restrict__ bias, float* __restrict__ out_f) {
    constexpr int TPB = 256;
    constexpr int BK = 128;
    constexpr int ROWB = BK * 2;               // 256 bytes per row
    constexpr int A_BYTES = BM * ROWB;         // 32 KB
    constexpr int B_BYTES = BN * ROWB;         // 64 KB
    constexpr int STG_BYTES = A_BYTES + B_BYTES;
    constexpr int SM_TILES = 2048;
    constexpr int MT = 4, PT = 4, NT = 8;      // 64x64 warp tile
    constexpr int K = GELU ? EMB : FF;
    constexpr int Npar = GELU ? FF : EMB;
    constexpr int NC = K / BK;

    extern __shared__ __align__(1024) uint8_t smem_raw[];
    uint32_t sb = smem_u32(smem_raw);
    const int tid = threadIdx.x;
    const int lane = tid & 31, warp = tid >> 5;
    const int wm = warp & 1;        // 0..1 -> 64-row slice
    const int wn = warp >> 1;       // 0..3 -> 64-col slice
    const int m0 = blockIdx.y * BM;
    const int n0 = blockIdx.x * BN;

    const __half* A = GELU ? g_Xh : g_H;
    const __half* B = GELU ? g_W1t : g_W2t;

    float* bias_s = reinterpret_cast<float*>(smem_raw);
    for (int i = tid; i < BN; i += TPB) bias_s[i] = bias[n0 + i];

    // ldmatrix lane -> row-offset / k-half mapping (validated R5/R7)
    const int a_roff = (lane & 7) + ((lane >> 3) & 1) * 8;
    const int a_hi   = (lane >> 4) & 1;
    const int b_noff = (lane & 7) + ((lane >> 4) & 1) * 8;
    const int b_hi   = (lane >> 3) & 1;

    float acc[MT][NT][4];
    #pragma unroll
    for (int mt = 0; mt < MT; mt++)
        #pragma unroll
        for (int nt = 0; nt < NT; nt++)
            #pragma unroll
            for (int e = 0; e < 4; e++) acc[mt][nt][e] = 0.f;

    uint32_t acch[FACC16 ? MT : 1][FACC16 ? NT : 1][2];
    if (FACC16) {
        #pragma unroll
        for (int mt = 0; mt < MT; mt++)
            #pragma unroll
            for (int nt = 0; nt < NT; nt++) { acch[mt][nt][0] = 0u; acch[mt][nt][1] = 0u; }
    }

    uint32_t a_rowb[MT]; int a_rc[MT];
    #pragma unroll
    for (int mt = 0; mt < MT; mt++) {
        int r = wm * 64 + mt * 16 + a_roff;
        a_rowb[mt] = r * ROWB; a_rc[mt] = r & 7;
    }
    uint32_t b_rowb[PT]; int b_rc[PT];
    #pragma unroll
    for (int p = 0; p < PT; p++) {
        int r = wn * 64 + p * 16 + b_noff;
        b_rowb[p] = r * ROWB; b_rc[p] = r & 7;
    }

    // tile loader: rows of 16 segs; swizzle seg' = seg ^ (row & 7) (banks repeat
    // every 128B, row stride 256B ≡ 0 mod 128 -> conflict-free for LDSM + CP16)
    auto load_tile = [&](int stage, int kc) {
        uint32_t sa = sb + SM_TILES + stage * STG_BYTES;
        uint32_t sB = sa + A_BYTES;
        #pragma unroll
        for (int t = 0; t < BM * 16 / TPB; t++) {
            int i = tid + t * TPB;
            int r = i >> 4, s = i & 15;
            uint32_t dst = sa + r * ROWB + ((s ^ (r & 7)) << 4);
            CP16(dst, A + (size_t)(m0 + r) * K + kc + s * 8);
        }
        #pragma unroll
        for (int t = 0; t < BN * 16 / TPB; t++) {
            int i = tid + t * TPB;
            int r = i >> 4, s = i & 15;
            uint32_t dst = sB + r * ROWB + ((s ^ (r & 7)) << 4);
            CP16(dst, B + (size_t)(n0 + r) * K + kc + s * 8);
        }
    };

    uint32_t ar[2][MT][4], br[2][PT][4];

    // prologue: both stages in flight
    load_tile(0, 0);  CP_COMMIT();
    load_tile(1, BK); CP_COMMIT();

    for (int i = 0; i < NC; i++) {
        CP_WAIT1();        // retire chunk i's group (one stays in flight)
        __syncthreads();   // chunk i's data visible CTA-wide
        uint32_t sa = sb + SM_TILES + (i & 1) * STG_BYTES;
        uint32_t sB = sa + A_BYTES;

        // kk=0 fragments -> buf 0
        #pragma unroll
        for (int mt = 0; mt < MT; mt++) {
            uint32_t ad = sa + a_rowb[mt] + ((a_hi ^ a_rc[mt]) << 4);
            LDSM4(ar[0][mt][0], ar[0][mt][1], ar[0][mt][2], ar[0][mt][3], ad);
        }
        #pragma unroll
        for (int p = 0; p < PT; p++) {
            uint32_t bd = sB + b_rowb[p] + ((b_hi ^ b_rc[p]) << 4);
            LDSM4(br[0][p][0], br[0][p][1], br[0][p][2], br[0][p][3], bd);
        }

        #pragma unroll
        for (int kk = 0; kk < 8; kk++) {
            const int cb = kk & 1, nb = cb ^ 1;
            if (kk < 7) {    // next-phase fragments
                const int s = 2 * (kk + 1);
                #pragma unroll
                for (int mt = 0; mt < MT; mt++) {
                    uint32_t ad = sa + a_rowb[mt] + (((s + a_hi) ^ a_rc[mt]) << 4);
                    LDSM4(ar[nb][mt][0], ar[nb][mt][1], ar[nb][mt][2], ar[nb][mt][3], ad);
                }
                #pragma unroll
                for (int p = 0; p < PT; p++) {
                    uint32_t bd = sB + b_rowb[p] + (((s + b_hi) ^ b_rc[p]) << 4);
                    LDSM4(br[nb][p][0], br[nb][p][1], br[nb][p][2], br[nb][p][3], bd);
                }
            }
            if (kk == 7) {
                // all warps issued their last LDSM of this stage (lockstep code):
                // safe to overwrite it with chunk i+2 while kk=7 MMAs run.
                __syncthreads();
                int pf = i + 2;
                if (pf < NC) load_tile(i & 1, pf * BK);
                CP_COMMIT();
            }
            #pragma unroll
            for (int mt = 0; mt < MT; mt++)
                #pragma unroll
                for (int nt = 0; nt < NT; nt++) {
                    int p = nt >> 1, h = (nt & 1) << 1;
                    if (FACC16) {
                        MMA16816H(acch[mt][nt],
                                  ar[cb][mt][0], ar[cb][mt][1], ar[cb][mt][2], ar[cb][mt][3],
                                  br[cb][p][h], br[cb][p][h + 1]);
                    } else {
                        MMA16816F(acc[mt][nt],
                                  ar[cb][mt][0], ar[cb][mt][1], ar[cb][mt][2], ar[cb][mt][3],
                                  br[cb][p][h], br[cb][p][h + 1]);
                    }
                }
        }

        if (FACC16) {   // promote chunk sum f16 -> f32 masters, reset f16 accs
            #pragma unroll
            for (int mt = 0; mt < MT; mt++)
                #pragma unroll
                for (int nt = 0; nt < NT; nt++) {
                    __half2 h0 = *reinterpret_cast<__half2*>(&acch[mt][nt][0]);
                    __half2 h1 = *reinterpret_cast<__half2*>(&acch[mt][nt][1]);
                    float2 f0 = __half22float2(h0);
                    float2 f1 = __half22float2(h1);
                    acc[mt][nt][0] += f0.x; acc[mt][nt][1] += f0.y;
                    acc[mt][nt][2] += f1.x; acc[mt][nt][3] += f1.y;
                    acch[mt][nt][0] = 0u;   acch[mt][nt][1] = 0u;
                }
        }
    }

    // ---------------- epilogue: fragments -> bias (+GELU) -> global ----------------
    const int mrow = lane >> 2;            // 0..7
    const int ncol = (lane & 3) * 2;       // 0,2,4,6
    #pragma unroll
    for (int mt = 0; mt < MT; mt++) {
        #pragma unroll
        for (int nt = 0; nt < NT; nt++) {
            int col_l = wn * 64 + nt * 8 + ncol;
            float bi0 = bias_s[col_l], bi1 = bias_s[col_l + 1];
            #pragma unroll
            for (int half = 0; half < 2; half++) {   // d0d1 (m+0) / d2d3 (m+8)
                int row = m0 + wm * 64 + mt * 16 + mrow + half * 8;
                float v0 = acc[mt][nt][2 * half]     + bi0;
                float v1 = acc[mt][nt][2 * half + 1] + bi1;
                if (GELU) {
                    v0 = 0.5f * v0 * (1.0f + erff(v0 * 0.70710678118654752f));
                    v1 = 0.5f * v1 * (1.0f + erff(v1 * 0.70710678118654752f));
                }
                size_t off = (size_t)row * Npar + n0 + col_l;
                if (GELU) {
                    __half2 h2 = __floats2half2_rn(v0, v1);
                    *reinterpret_cast<__half2*>(g_H + off) = h2;
                } else {
                    float2 f2; f2.x = v0; f2.y = v1;
                    *reinterpret_cast<float2*>(out_f + off) = f2;
                }
            }
        }
    }
}

// ---------------- preprocessing (3 launches) ----------------
__global__ void absmean_both_k(const float4* __restrict__ W1,
                               const float4* __restrict__ W2) {
    __shared__ float sm[256];
    const int half = blockIdx.x >> 10;               // 0: W1, 1: W2
    const int blk = blockIdx.x & 1023;
    const float4* w = half ? W2 : W1;
    float s = 0.f;
    const int total = WN_ / 4;
    for (int i = blk * 256 + threadIdx.x; i < total; i += 1024 * 256) {
        float4 v = w[i];
        s += fabsf(v.x) + fabsf(v.y) + fabsf(v.z) + fabsf(v.w);
    }
    sm[threadIdx.x] = s;
    __syncthreads();
    #pragma unroll
    for (int d = 128; d > 0; d >>= 1) {
        if (threadIdx.x < d) sm[threadIdx.x] += sm[threadIdx.x + d];
        __syncthreads();
    }
    if (threadIdx.x == 0) g_partial[half * 1024 + blk] = sm[0];
}

__global__ void absmean_final_k() {
    __shared__ float sm[1024];
    sm[threadIdx.x] = g_partial[blockIdx.x * 1024 + threadIdx.x];
    __syncthreads();
    #pragma unroll
    for (int d = 512; d > 0; d >>= 1) {
        if (threadIdx.x < d) sm[threadIdx.x] += sm[threadIdx.x + d];
        __syncthreads();
    }
    if (threadIdx.x == 0) g_scale[blockIdx.x] = fmaxf(sm[0] / (float)WN_, 1e-8f);
}

// one launch: quantize W1, W2 (ternary fp16) and convert x -> fp16
__global__ void prep_convert_k(const float4* __restrict__ W1,
                               const float4* __restrict__ W2,
                               const float4* __restrict__ x) {
    int i = blockIdx.x * 256 + threadIdx.x;
    const int Q = WN_ / 4;                   // 1M float4 per weight matrix
    uint2 u;
    if (i < 2 * Q) {
        int which = i >= Q;
        int j = i - which * Q;
        float inv = 1.0f / g_scale[which];
        float4 v = (which ? W2 : W1)[j];
        float a = fminf(fmaxf(rintf(v.x * inv), -1.f), 1.f);
        float b = fminf(fmaxf(rintf(v.y * inv), -1.f), 1.f);
        float c = fminf(fmaxf(rintf(v.z * inv), -1.f), 1.f);
        float d = fminf(fmaxf(rintf(v.w * inv), -1.f), 1.f);
        __half2 h0 = __floats2half2_rn(a, b);
        __half2 h1 = __floats2half2_rn(c, d);
        u.x = *reinterpret_cast<uint32_t*>(&h0);
        u.y = *reinterpret_cast<uint32_t*>(&h1);
        *reinterpret_cast<uint2*>((which ? g_W2t : g_W1t) + (size_t)j * 4) = u;
    } else {
        int j = i - 2 * Q;                  // 0 .. XN/4-1
        float4 v = x[j];
        __half2 h0 = __floats2half2_rn(v.x, v.y);
        __half2 h1 = __floats2half2_rn(v.z, v.w);
        u.x = *reinterpret_cast<uint32_t*>(&h0);
        u.y = *reinterpret_cast<uint32_t*>(&h1);
        *reinterpret_cast<uint2*>(g_Xh + (size_t)j * 4) = u;
    }
}

// ---------------- launcher ----------------
extern "C" void kernel_launch(void* const* d_in, const int* in_sizes, int n_in,
                              void* d_out, int out_size) {
    const float* x  = (const float*)d_in[0];
    const float* W1 = (const float*)d_in[1];
    const float* b1 = (const float*)d_in[2];
    const float* W2 = (const float*)d_in[3];
    const float* b2 = (const float*)d_in[4];
    float* out = (float*)d_out;

    // 2 stages x (32 KB A + 64 KB B) + 2 KB bias
    constexpr int SMEM = 2048 + 2 * (128 * 256 + 256 * 256);   // 198656

    cudaFuncSetAttribute((const void*)ffn_gemm<128, 256, true, true>,
                         cudaFuncAttributeMaxDynamicSharedMemorySize, SMEM);
    cudaFuncSetAttribute((const void*)ffn_gemm<128, 256, false, false>,
                         cudaFuncAttributeMaxDynamicSharedMemorySize, SMEM);

    absmean_both_k<<<2048, 256>>>((const float4*)W1, (const float4*)W2);
    absmean_final_k<<<2, 1024>>>();
    prep_convert_k<<<(2 * (WN_ / 4) + XN_ / 4) / 256, 256>>>(
        (const float4*)W1, (const float4*)W2, (const float4*)x);

    ffn_gemm<128, 256, true, true>
        <<<dim3(FF / 256, NTOK / 128), 256, SMEM>>>(b1, nullptr);
    ffn_gemm<128, 256, false, false>
        <<<dim3(EMB / 256, NTOK / 128), 256, SMEM>>>(b2, out);
}

// round 13
// speedup vs baseline: 1.0933x; 1.0642x over previous
// BitNet-style FFN on GB300 — sm_103 baseline-ISA build (tcgen05 rejected by the
// harness's ptxas). cp.async + ldmatrix + mma.sync.m16n8k16.f32.f16.f16.f32.
//   out = gelu_exact(x @ T(W1)^T + b1) @ T(W2)^T + b2,  T() = absmean ternary {-1,0,1}
// Ternary weights EXACT in fp16; x/H fp16, fp32 accumulators -> rel_err ~3e-4.
// R12: R11 decoded — BK=128/2-stage ran at ~10.4 cyc/MMA/SMSP (GEMM2) vs 13.5-14.2
//      for every BK=64 variant; the "floor" was per-chunk overhead. FACC16 spilled
//      (regs 255) and masked this. So: BOTH GEMMs get f32-acc + BK=128 + 2-stage;
//      GEMM2 also fixes its 1.73-wave tail via 64x128 tiles (1024 CTAs, 6.92 waves).

#include <cuda_runtime.h>
#include <cuda_fp16.h>
#include <cstdint>

#define EMB 1024
#define FF 4096
#define NTOK 8192
#define WN_ (FF * EMB)
#define XN_ (NTOK * EMB)

// ---------------- device-global scratch (allocation-free rule) ----------------
__device__ __align__(16) __half g_Xh[(size_t)NTOK * EMB];   // 16 MB
__device__ __align__(16) __half g_W1t[(size_t)FF * EMB];    // 8 MB
__device__ __align__(16) __half g_W2t[(size_t)FF * EMB];    // 8 MB
__device__ __align__(16) __half g_H[(size_t)NTOK * FF];     // 64 MB
__device__ float g_partial[2048];
__device__ float g_scale[2];

// ---------------- PTX helpers ----------------
__device__ __forceinline__ uint32_t smem_u32(const void* p) {
    uint32_t a;
    asm("{ .reg .u64 t; cvta.to.shared.u64 t, %1; cvt.u32.u64 %0, t; }" : "=r"(a) : "l"(p));
    return a;
}

#define CP16(dst, src) \
    asm volatile("cp.async.cg.shared.global [%0], [%1], 16;" \
                 :: "r"((uint32_t)(dst)), "l"(__cvta_generic_to_global(src)) : "memory")
#define CP_COMMIT()  asm volatile("cp.async.commit_group;" ::: "memory")
#define CP_WAIT1()   asm volatile("cp.async.wait_group 1;" ::: "memory")

#define LDSM4(r0, r1, r2, r3, addr) \
    asm volatile("ldmatrix.sync.aligned.m8n8.x4.shared.b16 {%0,%1,%2,%3}, [%4];" \
                 : "=r"(r0), "=r"(r1), "=r"(r2), "=r"(r3) : "r"(addr))

#define MMA16816F(d, a0, a1, a2, a3, b0, b1) \
    asm("mma.sync.aligned.m16n8k16.row.col.f32.f16.f16.f32 " \
        "{%0,%1,%2,%3}, {%4,%5,%6,%7}, {%8,%9}, {%0,%1,%2,%3};" \
        : "+f"((d)[0]), "+f"((d)[1]), "+f"((d)[2]), "+f"((d)[3]) \
        : "r"(a0), "r"(a1), "r"(a2), "r"(a3), "r"(b0), "r"(b1))

// ---------------- fused GEMM + epilogue ----------------
// BK = 128 (16 segs of 16B per row), 2 smem stages, 8 warps (TPB=256).
// Requires (BM/WM)*(BN/WN) == 8.
// GELU=true : A=g_Xh [8192,1024], B=g_W1t [4096,1024], out=g_H (fp16), +b1, erf-GELU
// GELU=false: A=g_H  [8192,4096], B=g_W2t [1024,4096], out=out_f (fp32), +b2
template <int BM, int BN, int WM, int WN, bool GELU>
__global__ void __launch_bounds__(256)
ffn_gemm(const float* __restrict__ bias, float* __restrict__ out_f) {
    constexpr int TPB = 256;
    constexpr int BK = 128;
    constexpr int ROWB = BK * 2;               // 256 bytes per row
    constexpr int A_BYTES = BM * ROWB;
    constexpr int B_BYTES = BN * ROWB;
    constexpr int STG_BYTES = A_BYTES + B_BYTES;
    constexpr int SM_TILES = 2048;
    constexpr int MT = WM / 16, PT = WN / 16, NT = WN / 8;
    constexpr int MW_CNT = BM / WM;
    constexpr int K = GELU ? EMB : FF;
    constexpr int Npar = GELU ? FF : EMB;
    constexpr int NC = K / BK;

    extern __shared__ __align__(1024) uint8_t smem_raw[];
    uint32_t sb = smem_u32(smem_raw);
    const int tid = threadIdx.x;
    const int lane = tid & 31, warp = tid >> 5;
    const int wm = warp % MW_CNT;
    const int wn = warp / MW_CNT;
    const int m0 = blockIdx.y * BM;
    const int n0 = blockIdx.x * BN;

    const __half* A = GELU ? g_Xh : g_H;
    const __half* B = GELU ? g_W1t : g_W2t;

    float* bias_s = reinterpret_cast<float*>(smem_raw);
    for (int i = tid; i < BN; i += TPB) bias_s[i] = bias[n0 + i];

    // ldmatrix lane -> row-offset / k-half mapping (validated R5/R7)
    const int a_roff = (lane & 7) + ((lane >> 3) & 1) * 8;
    const int a_hi   = (lane >> 4) & 1;
    const int b_noff = (lane & 7) + ((lane >> 4) & 1) * 8;
    const int b_hi   = (lane >> 3) & 1;

    float acc[MT][NT][4];
    #pragma unroll
    for (int mt = 0; mt < MT; mt++)
        #pragma unroll
        for (int nt = 0; nt < NT; nt++)
            #pragma unroll
            for (int e = 0; e < 4; e++) acc[mt][nt][e] = 0.f;

    uint32_t a_rowb[MT]; int a_rc[MT];
    #pragma unroll
    for (int mt = 0; mt < MT; mt++) {
        int r = wm * WM + mt * 16 + a_roff;
        a_rowb[mt] = r * ROWB; a_rc[mt] = r & 7;
    }
    uint32_t b_rowb[PT]; int b_rc[PT];
    #pragma unroll
    for (int p = 0; p < PT; p++) {
        int r = wn * WN + p * 16 + b_noff;
        b_rowb[p] = r * ROWB; b_rc[p] = r & 7;
    }

    // tile loader: 16 segs/row; swizzle seg' = seg ^ (row & 7); conflict-free
    auto load_tile = [&](int stage, int kc) {
        uint32_t sa = sb + SM_TILES + stage * STG_BYTES;
        uint32_t sB = sa + A_BYTES;
        #pragma unroll
        for (int t = 0; t < BM * 16 / TPB; t++) {
            int i = tid + t * TPB;
            int r = i >> 4, s = i & 15;
            uint32_t dst = sa + r * ROWB + ((s ^ (r & 7)) << 4);
            CP16(dst, A + (size_t)(m0 + r) * K + kc + s * 8);
        }
        #pragma unroll
        for (int t = 0; t < BN * 16 / TPB; t++) {
            int i = tid + t * TPB;
            int r = i >> 4, s = i & 15;
            uint32_t dst = sB + r * ROWB + ((s ^ (r & 7)) << 4);
            CP16(dst, B + (size_t)(n0 + r) * K + kc + s * 8);
        }
    };

    uint32_t ar[2][MT][4], br[2][PT][4];

    // prologue: both stages in flight
    load_tile(0, 0);  CP_COMMIT();
    load_tile(1, BK); CP_COMMIT();

    for (int i = 0; i < NC; i++) {
        CP_WAIT1();        // retire chunk i's group (one stays in flight)
        __syncthreads();   // chunk i's data visible CTA-wide
        uint32_t sa = sb + SM_TILES + (i & 1) * STG_BYTES;
        uint32_t sB = sa + A_BYTES;

        // kk=0 fragments -> buf 0
        #pragma unroll
        for (int mt = 0; mt < MT; mt++) {
            uint32_t ad = sa + a_rowb[mt] + ((a_hi ^ a_rc[mt]) << 4);
            LDSM4(ar[0][mt][0], ar[0][mt][1], ar[0][mt][2], ar[0][mt][3], ad);
        }
        #pragma unroll
        for (int p = 0; p < PT; p++) {
            uint32_t bd = sB + b_rowb[p] + ((b_hi ^ b_rc[p]) << 4);
            LDSM4(br[0][p][0], br[0][p][1], br[0][p][2], br[0][p][3], bd);
        }

        #pragma unroll
        for (int kk = 0; kk < 8; kk++) {
            const int cb = kk & 1, nb = cb ^ 1;
            if (kk < 7) {    // next-phase fragments
                const int s = 2 * (kk + 1);
                #pragma unroll
                for (int mt = 0; mt < MT; mt++) {
                    uint32_t ad = sa + a_rowb[mt] + (((s + a_hi) ^ a_rc[mt]) << 4);
                    LDSM4(ar[nb][mt][0], ar[nb][mt][1], ar[nb][mt][2], ar[nb][mt][3], ad);
                }
                #pragma unroll
                for (int p = 0; p < PT; p++) {
                    uint32_t bd = sB + b_rowb[p] + (((s + b_hi) ^ b_rc[p]) << 4);
                    LDSM4(br[nb][p][0], br[nb][p][1], br[nb][p][2], br[nb][p][3], bd);
                }
            }
            if (kk == 7) {
                // all warps issued their last LDSM of this stage (lockstep code):
                // safe to overwrite with chunk i+2 while kk=7 MMAs run.
                __syncthreads();
                int pf = i + 2;
                if (pf < NC) load_tile(i & 1, pf * BK);
                CP_COMMIT();
            }
            #pragma unroll
            for (int mt = 0; mt < MT; mt++)
                #pragma unroll
                for (int nt = 0; nt < NT; nt++) {
                    int p = nt >> 1, h = (nt & 1) << 1;
                    MMA16816F(acc[mt][nt],
                              ar[cb][mt][0], ar[cb][mt][1], ar[cb][mt][2], ar[cb][mt][3],
                              br[cb][p][h], br[cb][p][h + 1]);
                }
        }
    }

    // ---------------- epilogue: fragments -> bias (+GELU) -> global ----------------
    const int mrow = lane >> 2;            // 0..7
    const int ncol = (lane & 3) * 2;       // 0,2,4,6
    #pragma unroll
    for (int mt = 0; mt < MT; mt++) {
        #pragma unroll
        for (int nt = 0; nt < NT; nt++) {
            int col_l = wn * WN + nt * 8 + ncol;
            float bi0 = bias_s[col_l], bi1 = bias_s[col_l + 1];
            #pragma unroll
            for (int half = 0; half < 2; half++) {   // d0d1 (m+0) / d2d3 (m+8)
                int row = m0 + wm * WM + mt * 16 + mrow + half * 8;
                float v0 = acc[mt][nt][2 * half]     + bi0;
                float v1 = acc[mt][nt][2 * half + 1] + bi1;
                if (GELU) {
                    v0 = 0.5f * v0 * (1.0f + erff(v0 * 0.70710678118654752f));
                    v1 = 0.5f * v1 * (1.0f + erff(v1 * 0.70710678118654752f));
                }
                size_t off = (size_t)row * Npar + n0 + col_l;
                if (GELU) {
                    __half2 h2 = __floats2half2_rn(v0, v1);
                    *reinterpret_cast<__half2*>(g_H + off) = h2;
                } else {
                    float2 f2; f2.x = v0; f2.y = v1;
                    *reinterpret_cast<float2*>(out_f + off) = f2;
                }
            }
        }
    }
}

// ---------------- preprocessing (3 launches) ----------------
__global__ void absmean_both_k(const float4* __restrict__ W1,
                               const float4* __restrict__ W2) {
    __shared__ float sm[256];
    const int half = blockIdx.x >> 10;               // 0: W1, 1: W2
    const int blk = blockIdx.x & 1023;
    const float4* w = half ? W2 : W1;
    float s = 0.f;
    const int total = WN_ / 4;
    for (int i = blk * 256 + threadIdx.x; i < total; i += 1024 * 256) {
        float4 v = w[i];
        s += fabsf(v.x) + fabsf(v.y) + fabsf(v.z) + fabsf(v.w);
    }
    sm[threadIdx.x] = s;
    __syncthreads();
    #pragma unroll
    for (int d = 128; d > 0; d >>= 1) {
        if (threadIdx.x < d) sm[threadIdx.x] += sm[threadIdx.x + d];
        __syncthreads();
    }
    if (threadIdx.x == 0) g_partial[half * 1024 + blk] = sm[0];
}

__global__ void absmean_final_k() {
    __shared__ float sm[1024];
    sm[threadIdx.x] = g_partial[blockIdx.x * 1024 + threadIdx.x];
    __syncthreads();
    #pragma unroll
    for (int d = 512; d > 0; d >>= 1) {
        if (threadIdx.x < d) sm[threadIdx.x] += sm[threadIdx.x + d];
        __syncthreads();
    }
    if (threadIdx.x == 0) g_scale[blockIdx.x] = fmaxf(sm[0] / (float)WN_, 1e-8f);
}

// one launch: quantize W1, W2 (ternary fp16) and convert x -> fp16
__global__ void prep_convert_k(const float4* __restrict__ W1,
                               const float4* __restrict__ W2,
                               const float4* __restrict__ x) {
    int i = blockIdx.x * 256 + threadIdx.x;
    const int Q = WN_ / 4;                   // 1M float4 per weight matrix
    uint2 u;
    if (i < 2 * Q) {
        int which = i >= Q;
        int j = i - which * Q;
        float inv = 1.0f / g_scale[which];
        float4 v = (which ? W2 : W1)[j];
        float a = fminf(fmaxf(rintf(v.x * inv), -1.f), 1.f);
        float b = fminf(fmaxf(rintf(v.y * inv), -1.f), 1.f);
        float c = fminf(fmaxf(rintf(v.z * inv), -1.f), 1.f);
        float d = fminf(fmaxf(rintf(v.w * inv), -1.f), 1.f);
        __half2 h0 = __floats2half2_rn(a, b);
        __half2 h1 = __floats2half2_rn(c, d);
        u.x = *reinterpret_cast<uint32_t*>(&h0);
        u.y = *reinterpret_cast<uint32_t*>(&h1);
        *reinterpret_cast<uint2*>((which ? g_W2t : g_W1t) + (size_t)j * 4) = u;
    } else {
        int j = i - 2 * Q;                  // 0 .. XN/4-1
        float4 v = x[j];
        __half2 h0 = __floats2half2_rn(v.x, v.y);
        __half2 h1 = __floats2half2_rn(v.z, v.w);
        u.x = *reinterpret_cast<uint32_t*>(&h0);
        u.y = *reinterpret_cast<uint32_t*>(&h1);
        *reinterpret_cast<uint2*>(g_Xh + (size_t)j * 4) = u;
    }
}

// ---------------- launcher ----------------
extern "C" void kernel_launch(void* const* d_in, const int* in_sizes, int n_in,
                              void* d_out, int out_size) {
    const float* x  = (const float*)d_in[0];
    const float* W1 = (const float*)d_in[1];
    const float* b1 = (const float*)d_in[2];
    const float* W2 = (const float*)d_in[3];
    const float* b2 = (const float*)d_in[4];
    float* out = (float*)d_out;

    // GEMM1: 128x256 tiles, 64x64 warps -> grid (16,64) = 1024 CTAs (6.92 waves)
    constexpr int SM1 = 2048 + 2 * (128 * 256 + 256 * 256);   // 198656
    // GEMM2: 64x128 tiles, 32x32 warps -> grid (8,128) = 1024 CTAs (6.92 waves)
    constexpr int SM2 = 2048 + 2 * (64 * 256 + 128 * 256);    // 100352

    cudaFuncSetAttribute((const void*)ffn_gemm<128, 256, 64, 64, true>,
                         cudaFuncAttributeMaxDynamicSharedMemorySize, SM1);
    cudaFuncSetAttribute((const void*)ffn_gemm<64, 128, 32, 32, false>,
                         cudaFuncAttributeMaxDynamicSharedMemorySize, SM2);

    absmean_both_k<<<2048, 256>>>((const float4*)W1, (const float4*)W2);
    absmean_final_k<<<2, 1024>>>();
    prep_convert_k<<<(2 * (WN_ / 4) + XN_ / 4) / 256, 256>>>(
        (const float4*)W1, (const float4*)W2, (const float4*)x);

    ffn_gemm<128, 256, 64, 64, true>
        <<<dim3(FF / 256, NTOK / 128), 256, SM1>>>(b1, nullptr);
    ffn_gemm<64, 128, 32, 32, false>
        <<<dim3(EMB / 128, NTOK / 64), 256, SM2>>>(b2, out);
}

// round 15
// speedup vs baseline: 1.1234x; 1.0276x over previous
// BitNet-style FFN on GB300 — sm_103 baseline-ISA build (tcgen05 rejected by the
// harness's ptxas). cp.async + ldmatrix + mma.sync.m16n8k16.f32.f16.f16.f32.
//   out = gelu_exact(x @ T(W1)^T + b1) @ T(W2)^T + b2,  T() = absmean ternary {-1,0,1}
// Ternary weights EXACT in fp16; x/H fp16, fp32 accumulators -> rel_err ~3e-4.
// R15: R14 rerun with the pipeline bug FIXED. R14's generic prologue loaded only
//      NST-1 chunks; for NST=2 chunk 1 was never loaded -> garbage smem -> NaN.
//      Now: prologue ALWAYS puts chunks 0,1 in flight; head cp_wait<1>; prefetch
//      chunk i+2 (head for NST>=3, at kk==NK-1 for NST=2). The R14 experiment —
//      GEMM1 at 2 CTAs/SM so co-resident CTAs overlap LDSM/MMA phases — stands.

#include <cuda_runtime.h>
#include <cuda_fp16.h>
#include <cstdint>

#define EMB 1024
#define FF 4096
#define NTOK 8192
#define WN_ (FF * EMB)
#define XN_ (NTOK * EMB)

// ---------------- device-global scratch (allocation-free rule) ----------------
__device__ __align__(16) __half g_Xh[(size_t)NTOK * EMB];   // 16 MB
__device__ __align__(16) __half g_W1t[(size_t)FF * EMB];    // 8 MB
__device__ __align__(16) __half g_W2t[(size_t)FF * EMB];    // 8 MB
__device__ __align__(16) __half g_H[(size_t)NTOK * FF];     // 64 MB
__device__ float g_partial[2048];
__device__ float g_scale[2];

// ---------------- PTX helpers ----------------
__device__ __forceinline__ uint32_t smem_u32(const void* p) {
    uint32_t a;
    asm("{ .reg .u64 t; cvta.to.shared.u64 t, %1; cvt.u32.u64 %0, t; }" : "=r"(a) : "l"(p));
    return a;
}

#define CP16(dst, src) \
    asm volatile("cp.async.cg.shared.global [%0], [%1], 16;" \
                 :: "r"((uint32_t)(dst)), "l"(__cvta_generic_to_global(src)) : "memory")
#define CP_COMMIT()  asm volatile("cp.async.commit_group;" ::: "memory")
#define CP_WAIT1()   asm volatile("cp.async.wait_group 1;" ::: "memory")

#define LDSM4(r0, r1, r2, r3, addr) \
    asm volatile("ldmatrix.sync.aligned.m8n8.x4.shared.b16 {%0,%1,%2,%3}, [%4];" \
                 : "=r"(r0), "=r"(r1), "=r"(r2), "=r"(r3) : "r"(addr))

#define MMA16816F(d, a0, a1, a2, a3, b0, b1) \
    asm("mma.sync.aligned.m16n8k16.row.col.f32.f16.f16.f32 " \
        "{%0,%1,%2,%3}, {%4,%5,%6,%7}, {%8,%9}, {%0,%1,%2,%3};" \
        : "+f"((d)[0]), "+f"((d)[1]), "+f"((d)[2]), "+f"((d)[3]) \
        : "r"(a0), "r"(a1), "r"(a2), "r"(a3), "r"(b0), "r"(b1))

// ---------------- fused GEMM + epilogue ----------------
// 8 warps (TPB=256), 2 CTAs/SM target. (BM/WM)*(BN/WN) must == 8. NC must be >= 2.
// Pipeline invariant: chunks i, i+1 in flight at head of iteration i (2 groups);
// chunk j lives in stage j % NST.
// DBUF: double-buffered fragments (use when regs allow).
// GELU=true : A=g_Xh [8192,1024], B=g_W1t [4096,1024], out=g_H (fp16), +b1, erf-GELU
// GELU=false: A=g_H  [8192,4096], B=g_W2t [1024,4096], out=out_f (fp32), +b2
template <int BM, int BN, int WM, int WN, int BK, int NST, bool DBUF, bool GELU>
__global__ void __launch_bounds__(256, 2)
ffn_gemm(const float* __restrict__ bias, float* __restrict__ out_f) {
    constexpr int TPB = 256;
    constexpr int ROWB = BK * 2;              // bytes per smem row
    constexpr int SEGS = BK / 8;              // 16B segs per row
    constexpr int A_BYTES = BM * ROWB;
    constexpr int B_BYTES = BN * ROWB;
    constexpr int STG_BYTES = A_BYTES + B_BYTES;
    constexpr int SM_TILES = 2048;
    constexpr int MT = WM / 16, PT = WN / 16, NT = WN / 8;
    constexpr int MW_CNT = BM / WM;
    constexpr int NK = BK / 16;               // k16 phases per chunk
    constexpr int K = GELU ? EMB : FF;
    constexpr int Npar = GELU ? FF : EMB;
    constexpr int NC = K / BK;
    static_assert(NC >= 2, "pipeline needs >= 2 chunks");

    extern __shared__ __align__(1024) uint8_t smem_raw[];
    uint32_t sb = smem_u32(smem_raw);
    const int tid = threadIdx.x;
    const int lane = tid & 31, warp = tid >> 5;
    const int wm = warp % MW_CNT;
    const int wn = warp / MW_CNT;
    const int m0 = blockIdx.y * BM;
    const int n0 = blockIdx.x * BN;

    const __half* A = GELU ? g_Xh : g_H;
    const __half* B = GELU ? g_W1t : g_W2t;

    float* bias_s = reinterpret_cast<float*>(smem_raw);
    for (int i = tid; i < BN; i += TPB) bias_s[i] = bias[n0 + i];

    // ldmatrix lane -> row-offset / k-half mapping (validated R5/R7)
    const int a_roff = (lane & 7) + ((lane >> 3) & 1) * 8;
    const int a_hi   = (lane >> 4) & 1;
    const int b_noff = (lane & 7) + ((lane >> 4) & 1) * 8;
    const int b_hi   = (lane >> 3) & 1;

    float acc[MT][NT][4];
    #pragma unroll
    for (int mt = 0; mt < MT; mt++)
        #pragma unroll
        for (int nt = 0; nt < NT; nt++)
            #pragma unroll
            for (int e = 0; e < 4; e++) acc[mt][nt][e] = 0.f;

    uint32_t a_rowb[MT]; int a_rc[MT];
    #pragma unroll
    for (int mt = 0; mt < MT; mt++) {
        int r = wm * WM + mt * 16 + a_roff;
        a_rowb[mt] = r * ROWB; a_rc[mt] = r & 7;
    }
    uint32_t b_rowb[PT]; int b_rc[PT];
    #pragma unroll
    for (int p = 0; p < PT; p++) {
        int r = wn * WN + p * 16 + b_noff;
        b_rowb[p] = r * ROWB; b_rc[p] = r & 7;
    }

    // tile loader: SEGS 16B segs/row; swizzle seg' = seg ^ (row & 7)
    auto load_tile = [&](int stage, int kc) {
        uint32_t sa = sb + SM_TILES + stage * STG_BYTES;
        uint32_t sB = sa + A_BYTES;
        #pragma unroll
        for (int t = 0; t < BM * SEGS / TPB; t++) {
            int i = tid + t * TPB;
            int r = i / SEGS, s = i % SEGS;
            uint32_t dst = sa + r * ROWB + ((s ^ (r & 7)) << 4);
            CP16(dst, A + (size_t)(m0 + r) * K + kc + s * 8);
        }
        #pragma unroll
        for (int t = 0; t < BN * SEGS / TPB; t++) {
            int i = tid + t * TPB;
            int r = i / SEGS, s = i % SEGS;
            uint32_t dst = sB + r * ROWB + ((s ^ (r & 7)) << 4);
            CP16(dst, B + (size_t)(n0 + r) * K + kc + s * 8);
        }
    };

    // prologue: chunks 0 and 1 in flight (2 groups) — pipeline invariant
    load_tile(0, 0);        CP_COMMIT();
    load_tile(1 % NST, BK); CP_COMMIT();

    for (int i = 0; i < NC; i++) {
        CP_WAIT1();        // retire chunk i's group (chunk i+1 stays in flight)
        __syncthreads();   // chunk i visible CTA-wide; prior readers of the
                           // stage we're about to refill are done
        uint32_t sa = sb + SM_TILES + (i % NST) * STG_BYTES;
        uint32_t sB = sa + A_BYTES;

        if (NST >= 3) {    // free stage exists: prefetch chunk i+2 now
            int pf = i + 2;
            if (pf < NC) load_tile(pf % NST, pf * BK);
            CP_COMMIT();
        }

        if constexpr (DBUF) {
            uint32_t ar[2][MT][4], br[2][PT][4];
            #pragma unroll
            for (int mt = 0; mt < MT; mt++) {
                uint32_t ad = sa + a_rowb[mt] + ((a_hi ^ a_rc[mt]) << 4);
                LDSM4(ar[0][mt][0], ar[0][mt][1], ar[0][mt][2], ar[0][mt][3], ad);
            }
            #pragma unroll
            for (int p = 0; p < PT; p++) {
                uint32_t bd = sB + b_rowb[p] + ((b_hi ^ b_rc[p]) << 4);
                LDSM4(br[0][p][0], br[0][p][1], br[0][p][2], br[0][p][3], bd);
            }
            #pragma unroll
            for (int kk = 0; kk < NK; kk++) {
                const int cb = kk & 1, nb = cb ^ 1;
                if (kk < NK - 1) {
                    const int s = 2 * (kk + 1);
                    #pragma unroll
                    for (int mt = 0; mt < MT; mt++) {
                        uint32_t ad = sa + a_rowb[mt] + (((s + a_hi) ^ a_rc[mt]) << 4);
                        LDSM4(ar[nb][mt][0], ar[nb][mt][1], ar[nb][mt][2], ar[nb][mt][3], ad);
                    }
                    #pragma unroll
                    for (int p = 0; p < PT; p++) {
                        uint32_t bd = sB + b_rowb[p] + (((s + b_hi) ^ b_rc[p]) << 4);
                        LDSM4(br[nb][p][0], br[nb][p][1], br[nb][p][2], br[nb][p][3], bd);
                    }
                }
                if (NST == 2 && kk == NK - 1) {
                    // all warps issued their final LDSM of this stage (lockstep
                    // code): safe to refill it with chunk i+2 under the MMAs.
                    __syncthreads();
                    int pf = i + 2;
                    if (pf < NC) load_tile(i % NST, pf * BK);
                    CP_COMMIT();
                }
                #pragma unroll
                for (int mt = 0; mt < MT; mt++)
                    #pragma unroll
                    for (int nt = 0; nt < NT; nt++) {
                        int p = nt >> 1, h = (nt & 1) << 1;
                        MMA16816F(acc[mt][nt],
                                  ar[cb][mt][0], ar[cb][mt][1], ar[cb][mt][2], ar[cb][mt][3],
                                  br[cb][p][h], br[cb][p][h + 1]);
                    }
            }
        } else {
            // single-buffered (low-reg) path: phased LDSM -> MMA per kk.
            // Intra-CTA serialization is covered by the co-resident CTA.
            static_assert(NST >= 3, "single-buffer path needs head prefetch");
            uint32_t ar[MT][4], br[PT][4];
            #pragma unroll
            for (int kk = 0; kk < NK; kk++) {
                const int s = 2 * kk;
                #pragma unroll
                for (int mt = 0; mt < MT; mt++) {
                    uint32_t ad = sa + a_rowb[mt] + (((s + a_hi) ^ a_rc[mt]) << 4);
                    LDSM4(ar[mt][0], ar[mt][1], ar[mt][2], ar[mt][3], ad);
                }
                #pragma unroll
                for (int p = 0; p < PT; p++) {
                    uint32_t bd = sB + b_rowb[p] + (((s + b_hi) ^ b_rc[p]) << 4);
                    LDSM4(br[p][0], br[p][1], br[p][2], br[p][3], bd);
                }
                #pragma unroll
                for (int mt = 0; mt < MT; mt++)
                    #pragma unroll
                    for (int nt = 0; nt < NT; nt++) {
                        int p = nt >> 1, h = (nt & 1) << 1;
                        MMA16816F(acc[mt][nt],
                                  ar[mt][0], ar[mt][1], ar[mt][2], ar[mt][3],
                                  br[p][h], br[p][h + 1]);
                    }
            }
        }
    }

    // ---------------- epilogue: fragments -> bias (+GELU) -> global ----------------
    const int mrow = lane >> 2;            // 0..7
    const int ncol = (lane & 3) * 2;       // 0,2,4,6
    #pragma unroll
    for (int mt = 0; mt < MT; mt++) {
        #pragma unroll
        for (int nt = 0; nt < NT; nt++) {
            int col_l = wn * WN + nt * 8 + ncol;
            float bi0 = bias_s[col_l], bi1 = bias_s[col_l + 1];
            #pragma unroll
            for (int half = 0; half < 2; half++) {   // d0d1 (m+0) / d2d3 (m+8)
                int row = m0 + wm * WM + mt * 16 + mrow + half * 8;
                float v0 = acc[mt][nt][2 * half]     + bi0;
                float v1 = acc[mt][nt][2 * half + 1] + bi1;
                if (GELU) {
                    v0 = 0.5f * v0 * (1.0f + erff(v0 * 0.70710678118654752f));
                    v1 = 0.5f * v1 * (1.0f + erff(v1 * 0.70710678118654752f));
                }
                size_t off = (size_t)row * Npar + n0 + col_l;
                if (GELU) {
                    __half2 h2 = __floats2half2_rn(v0, v1);
                    *reinterpret_cast<__half2*>(g_H + off) = h2;
                } else {
                    float2 f2; f2.x = v0; f2.y = v1;
                    *reinterpret_cast<float2*>(out_f + off) = f2;
                }
            }
        }
    }
}

// ---------------- preprocessing (3 launches) ----------------
__global__ void absmean_both_k(const float4* __restrict__ W1,
                               const float4* __restrict__ W2) {
    __shared__ float sm[256];
    const int half = blockIdx.x >> 10;               // 0: W1, 1: W2
    const int blk = blockIdx.x & 1023;
    const float4* w = half ? W2 : W1;
    float s = 0.f;
    const int total = WN_ / 4;
    for (int i = blk * 256 + threadIdx.x; i < total; i += 1024 * 256) {
        float4 v = w[i];
        s += fabsf(v.x) + fabsf(v.y) + fabsf(v.z) + fabsf(v.w);
    }
    sm[threadIdx.x] = s;
    __syncthreads();
    #pragma unroll
    for (int d = 128; d > 0; d >>= 1) {
        if (threadIdx.x < d) sm[threadIdx.x] += sm[threadIdx.x + d];
        __syncthreads();
    }
    if (threadIdx.x == 0) g_partial[half * 1024 + blk] = sm[0];
}

__global__ void absmean_final_k() {
    __shared__ float sm[1024];
    sm[threadIdx.x] = g_partial[blockIdx.x * 1024 + threadIdx.x];
    __syncthreads();
    #pragma unroll
    for (int d = 512; d > 0; d >>= 1) {
        if (threadIdx.x < d) sm[threadIdx.x] += sm[threadIdx.x + d];
        __syncthreads();
    }
    if (threadIdx.x == 0) g_scale[blockIdx.x] = fmaxf(sm[0] / (float)WN_, 1e-8f);
}

// one launch: quantize W1, W2 (ternary fp16) and convert x -> fp16
__global__ void prep_convert_k(const float4* __restrict__ W1,
                               const float4* __restrict__ W2,
                               const float4* __restrict__ x) {
    int i = blockIdx.x * 256 + threadIdx.x;
    const int Q = WN_ / 4;                   // 1M float4 per weight matrix
    uint2 u;
    if (i < 2 * Q) {
        int which = i >= Q;
        int j = i - which * Q;
        float inv = 1.0f / g_scale[which];
        float4 v = (which ? W2 : W1)[j];
        float a = fminf(fmaxf(rintf(v.x * inv), -1.f), 1.f);
        float b = fminf(fmaxf(rintf(v.y * inv), -1.f), 1.f);
        float c = fminf(fmaxf(rintf(v.z * inv), -1.f), 1.f);
        float d = fminf(fmaxf(rintf(v.w * inv), -1.f), 1.f);
        __half2 h0 = __floats2half2_rn(a, b);
        __half2 h1 = __floats2half2_rn(c, d);
        u.x = *reinterpret_cast<uint32_t*>(&h0);
        u.y = *reinterpret_cast<uint32_t*>(&h1);
        *reinterpret_cast<uint2*>((which ? g_W2t : g_W1t) + (size_t)j * 4) = u;
    } else {
        int j = i - 2 * Q;                  // 0 .. XN/4-1
        float4 v = x[j];
        __half2 h0 = __floats2half2_rn(v.x, v.y);
        __half2 h1 = __floats2half2_rn(v.z, v.w);
        u.x = *reinterpret_cast<uint32_t*>(&h0);
        u.y = *reinterpret_cast<uint32_t*>(&h1);
        *reinterpret_cast<uint2*>(g_Xh + (size_t)j * 4) = u;
    }
}

// ---------------- launcher ----------------
extern "C" void kernel_launch(void* const* d_in, const int* in_sizes, int n_in,
                              void* d_out, int out_size) {
    const float* x  = (const float*)d_in[0];
    const float* W1 = (const float*)d_in[1];
    const float* b1 = (const float*)d_in[2];
    const float* W2 = (const float*)d_in[3];
    const float* b2 = (const float*)d_in[4];
    float* out = (float*)d_out;

    // GEMM1: CTA 128x128, warp 64x32, BK=64, 3 stages, single-buffer frags.
    //        smem = 2048 + 3*32768 = 100352 -> 2 CTAs/SM. grid 32x64 = 2048 CTAs.
    constexpr int SM1 = 2048 + 3 * (128 * 128 + 128 * 128);
    // GEMM2: CTA 64x128, warp 32x32, BK=128, 2 stages, double-buffer frags (R13).
    //        smem = 2048 + 2*49152 = 100352 -> 2 CTAs/SM. grid 8x128 = 1024 CTAs.
    constexpr int SM2 = 2048 + 2 * (64 * 256 + 128 * 256);

    cudaFuncSetAttribute((const void*)ffn_gemm<128, 128, 64, 32, 64, 3, false, true>,
                         cudaFuncAttributeMaxDynamicSharedMemorySize, SM1);
    cudaFuncSetAttribute((const void*)ffn_gemm<64, 128, 32, 32, 128, 2, true, false>,
                         cudaFuncAttributeMaxDynamicSharedMemorySize, SM2);

    absmean_both_k<<<2048, 256>>>((const float4*)W1, (const float4*)W2);
    absmean_final_k<<<2, 1024>>>();
    prep_convert_k<<<(2 * (WN_ / 4) + XN_ / 4) / 256, 256>>>(
        (const float4*)W1, (const float4*)W2, (const float4*)x);

    ffn_gemm<128, 128, 64, 32, 64, 3, false, true>
        <<<dim3(FF / 128, NTOK / 128), 256, SM1>>>(b1, nullptr);
    ffn_gemm<64, 128, 32, 32, 128, 2, true, false>
        <<<dim3(EMB / 128, NTOK / 64), 256, SM2>>>(b2, out);
}